// round 10
// baseline (speedup 1.0000x reference)
#include <cuda_runtime.h>
#include <cuda_bf16.h>
#include <math.h>

// Problem constants
#define B_ 2
#define T_ 2048
#define E_ 2048
#define H_ 16
#define KVH_ 8
#define D_ 128
#define SCALE_ 0.08838834764831845f   // 1/sqrt(128)

typedef unsigned long long ull;

// ---------------- packed f32x2 helpers ----------------
__device__ __forceinline__ ull pk2(float lo, float hi) {
    ull r; asm("mov.b64 %0, {%1, %2};" : "=l"(r) : "f"(lo), "f"(hi)); return r;
}
__device__ __forceinline__ void upk2(ull v, float& lo, float& hi) {
    asm("mov.b64 {%0, %1}, %2;" : "=f"(lo), "=f"(hi) : "l"(v));
}
__device__ __forceinline__ void fma2(ull& d, ull a, ull b) {
    asm("fma.rn.f32x2 %0, %1, %2, %0;" : "+l"(d) : "l"(a), "l"(b));
}
__device__ __forceinline__ void mul2(ull& d, ull a) {
    asm("mul.rn.f32x2 %0, %0, %1;" : "+l"(d) : "l"(a));
}

// ---------------- scratch ----------------
__device__ float g_q[(size_t)B_ * T_ * H_ * D_];
__device__ float g_k[(size_t)B_ * T_ * KVH_ * D_];
__device__ float g_v[(size_t)B_ * T_ * KVH_ * D_];
__device__ float g_ctx[(size_t)B_ * T_ * H_ * D_];
__device__ float2 g_rope[T_ * 64];

// ---------------- RoPE table ----------------
__global__ __launch_bounds__(256) void rope_table_kernel() {
    int idx = blockIdx.x * 256 + threadIdx.x;
    int t = idx >> 6, d2 = idx & 63;
    double inv = pow(10000.0, -(double)(2 * d2) / 128.0);
    double ang = (double)t * inv;
    g_rope[idx] = make_float2((float)cos(ang), (float)sin(ang));
}

// ---------------- RoPE apply ----------------
__global__ __launch_bounds__(256) void rope_apply_kernel(float* __restrict__ x, int heads, int total4) {
    int p = blockIdx.x * 256 + threadIdx.x;
    if (p >= total4) return;
    int cd = p & 31;
    int t = (p / (32 * heads)) % T_;
    float4 v = ((const float4*)x)[p];
    float2 r0 = g_rope[t * 64 + cd * 2];
    float2 r1 = g_rope[t * 64 + cd * 2 + 1];
    float a = v.x * r0.x - v.y * r0.y;
    float b = v.x * r0.y + v.y * r0.x;
    float c = v.z * r1.x - v.w * r1.y;
    float d = v.z * r1.y + v.w * r1.x;
    ((float4*)x)[p] = make_float4(a, b, c, d);
}

// ---------------- SGEMM (BK=16, padded As, 2 CTAs/SM) ----------------
__device__ __forceinline__ void sgemm_compute(
    const float As[16][132], const float Bs[16][128],
    int ty, int tx, ull acc[8][4])
{
#pragma unroll
    for (int kk = 0; kk < 16; kk++) {
        float ar[8];
        *(float4*)(ar)     = *(const float4*)&As[kk][ty * 8];
        *(float4*)(ar + 4) = *(const float4*)&As[kk][ty * 8 + 4];
        ulonglong2 b0 = *(const ulonglong2*)&Bs[kk][tx * 8];
        ulonglong2 b1 = *(const ulonglong2*)&Bs[kk][tx * 8 + 4];
        ull br0 = b0.x, br1 = b0.y, br2 = b1.x, br3 = b1.y;
#pragma unroll
        for (int i = 0; i < 8; i++) {
            ull a2 = pk2(ar[i], ar[i]);
            fma2(acc[i][0], a2, br0);
            fma2(acc[i][1], a2, br1);
            fma2(acc[i][2], a2, br2);
            fma2(acc[i][3], a2, br3);
        }
    }
}

__global__ __launch_bounds__(256, 2) void sgemm_kernel(
    const float* __restrict__ A, const float* __restrict__ Bm,
    float* __restrict__ C, int M, int N, int K)
{
    __shared__ float As[2][16][132];
    __shared__ float Bs[2][16][128];

    const int tid = threadIdx.x;
    const int bx = blockIdx.x, by = blockIdx.y;
    const int arow = tid >> 2;
    const int acol = (tid & 3) * 4;
    const int brow = tid >> 5;
    const int bcol = (tid & 31) << 2;
    const int tx = tid & 15, ty = tid >> 4;

    const float* Ag = A + (size_t)(by * 128 + arow) * K + acol;
    const float* Bg = Bm + (size_t)brow * N + bx * 128 + bcol;

    ull acc[8][4];
#pragma unroll
    for (int i = 0; i < 8; i++)
#pragma unroll
        for (int j = 0; j < 4; j++) acc[i][j] = 0ull;

    float4 av0 = *(const float4*)Ag;
    float4 av1 = *(const float4*)(Ag + (size_t)64 * K);
    Ag += 16;
    float4 bv0 = *(const float4*)Bg;
    float4 bv1 = *(const float4*)(Bg + (size_t)8 * N);
    Bg += (size_t)16 * N;
    As[0][acol + 0][arow] = av0.x;  As[0][acol + 1][arow] = av0.y;
    As[0][acol + 2][arow] = av0.z;  As[0][acol + 3][arow] = av0.w;
    As[0][acol + 0][arow + 64] = av1.x;  As[0][acol + 1][arow + 64] = av1.y;
    As[0][acol + 2][arow + 64] = av1.z;  As[0][acol + 3][arow + 64] = av1.w;
    *(float4*)&Bs[0][brow][bcol] = bv0;
    *(float4*)&Bs[0][brow + 8][bcol] = bv1;
    __syncthreads();

    const int nch = K >> 4;
    for (int c = 1; c < nch; ++c) {
        av0 = *(const float4*)Ag;
        av1 = *(const float4*)(Ag + (size_t)64 * K);
        Ag += 16;
        bv0 = *(const float4*)Bg;
        bv1 = *(const float4*)(Bg + (size_t)8 * N);
        Bg += (size_t)16 * N;
        const int cur = (c - 1) & 1;
        sgemm_compute(As[cur], Bs[cur], ty, tx, acc);
        const int nxt = c & 1;
        As[nxt][acol + 0][arow] = av0.x;  As[nxt][acol + 1][arow] = av0.y;
        As[nxt][acol + 2][arow] = av0.z;  As[nxt][acol + 3][arow] = av0.w;
        As[nxt][acol + 0][arow + 64] = av1.x;  As[nxt][acol + 1][arow + 64] = av1.y;
        As[nxt][acol + 2][arow + 64] = av1.z;  As[nxt][acol + 3][arow + 64] = av1.w;
        *(float4*)&Bs[nxt][brow][bcol] = bv0;
        *(float4*)&Bs[nxt][brow + 8][bcol] = bv1;
        __syncthreads();
    }
    sgemm_compute(As[(nch - 1) & 1], Bs[(nch - 1) & 1], ty, tx, acc);

    float* Cp = C + (size_t)(by * 128 + ty * 8) * N + bx * 128 + tx * 8;
#pragma unroll
    for (int i = 0; i < 8; i++) {
        float cf[8];
#pragma unroll
        for (int j = 0; j < 4; j++) upk2(acc[i][j], cf[2 * j], cf[2 * j + 1]);
        *(float4*)(Cp + (size_t)i * N)     = make_float4(cf[0], cf[1], cf[2], cf[3]);
        *(float4*)(Cp + (size_t)i * N + 4) = make_float4(cf[4], cf[5], cf[6], cf[7]);
    }
}

// ---------------- Flash attention: warp-owns-16-rows, broadcast-operand FFMA2 ----------------
// 256 threads, 8 warps. Warp w owns query rows 16w..16w+15 (all lanes share rows).
// Lane covers kv-cols {4*lane..+3} (phase A) / d {4*lane..+3} (phase B).
// Q/P loaded as warp-uniform broadcast ulonglong2 row-pairs (packed f32x2 operands
// directly); pk2 only on K/V scalars, each amortized over 8 fma2.
// Layouts:
//   Qt [kd][r]:  phys float = kd*128 + (r ^ (4*((kd>>2)&7)))  -> chunk (r>>2)^((kd>>2)&7)
//   Ks/Vs [row][d-chunk]: phys chunk = cd ^ ((row>>2)&7)
//   Pt [j][r-chunk] (aliases Ks): phys chunk = (r>>2) ^ ((j>>2)&7)
#define FT 128
#define FLASH_SMEM_BYTES (3 * 128 * 128 * 4)

__global__ __launch_bounds__(256) void flash_kernel(
    const float* __restrict__ q, const float* __restrict__ k,
    const float* __restrict__ v, float* __restrict__ ctx)
{
    extern __shared__ float sm[];
    float* Qt = sm;                         // 16384 floats
    float* KP = sm + 16384;                 // K tile, later Pt
    float* Vs = sm + 32768;                 // V tile
    float4* KP4 = (float4*)KP;
    float4* Vs4 = (float4*)Vs;
    const ulonglong2* Qt2 = (const ulonglong2*)Qt;
    const ulonglong2* KPl2 = (const ulonglong2*)KP;

    const int qt_ = (int)gridDim.x - 1 - (int)blockIdx.x;  // heavy blocks first
    const int bh = blockIdx.y;
    const int b = bh >> 4;
    const int h = bh & 15;
    const int g = h >> 1;
    const int tid = threadIdx.x;
    const int lane = tid & 31, w = tid >> 5;
    const int r0 = w * 16;
    const int rq0 = w * 4;          // r-chunk base for this warp
    const int sw8 = lane & 7;

    // ---- load Q tile, scale, store transposed + swizzled ----
    const size_t qbase = (((size_t)b * T_ + (size_t)qt_ * FT) * H_ + h) * D_;
#pragma unroll
    for (int it = 0; it < 16; ++it) {
        int f = it * 256 + tid;
        int r = f >> 5, cd = f & 31;
        float4 val = *(const float4*)(q + qbase + (size_t)r * (H_ * D_) + cd * 4);
        val.x *= SCALE_; val.y *= SCALE_; val.z *= SCALE_; val.w *= SCALE_;
        int rp = r ^ (4 * (cd & 7));
        Qt[(4 * cd + 0) * 128 + rp] = val.x;
        Qt[(4 * cd + 1) * 128 + rp] = val.y;
        Qt[(4 * cd + 2) * 128 + rp] = val.z;
        Qt[(4 * cd + 3) * 128 + rp] = val.w;
    }

    float m_[16], l_[16];
#pragma unroll
    for (int i = 0; i < 16; i++) { m_[i] = -1e30f; l_[i] = 0.0f; }

    ull o2[8][4];
#pragma unroll
    for (int p = 0; p < 8; p++)
#pragma unroll
        for (int dd = 0; dd < 4; dd++) o2[p][dd] = 0ull;

    __syncthreads();

    for (int kt = 0; kt <= qt_; ++kt) {
        // ---- load K,V tiles (row-major, swizzled chunks) ----
        const size_t kvbase = (((size_t)b * T_ + (size_t)kt * FT) * KVH_ + g) * D_;
#pragma unroll
        for (int it = 0; it < 16; ++it) {
            int f = it * 256 + tid;
            int r = f >> 5, cd = f & 31;
            size_t off = kvbase + (size_t)r * (KVH_ * D_) + cd * 4;
            int sidx = r * 32 + (cd ^ ((r >> 2) & 7));
            KP4[sidx] = *(const float4*)(k + off);
            Vs4[sidx] = *(const float4*)(v + off);
        }
        __syncthreads();

        // ---- phase A: S = Q K^T ; accum packed row-pairs ----
        ull s2[8][4];
#pragma unroll
        for (int p = 0; p < 8; p++)
#pragma unroll
            for (int jj = 0; jj < 4; jj++) s2[p][jj] = 0ull;

#pragma unroll 2
        for (int kc = 0; kc < 32; ++kc) {
            float4 kf[4];
#pragma unroll
            for (int jj = 0; jj < 4; ++jj)
                kf[jj] = KP4[(4 * lane + jj) * 32 + (kc ^ sw8)];
            const int sws = kc & 7;
#pragma unroll
            for (int kd4 = 0; kd4 < 4; ++kd4) {
                const int kbase = (kc * 4 + kd4) * 32;
                ull qp[8];
#pragma unroll
                for (int cc = 0; cc < 4; ++cc) {
                    ulonglong2 t = Qt2[kbase + ((rq0 + cc) ^ sws)];
                    qp[2 * cc] = t.x; qp[2 * cc + 1] = t.y;
                }
#pragma unroll
                for (int jj = 0; jj < 4; ++jj) {
                    float kvv = ((const float*)&kf[jj])[kd4];
                    ull kdp = pk2(kvv, kvv);
#pragma unroll
                    for (int p = 0; p < 8; ++p) fma2(s2[p][jj], qp[p], kdp);
                }
            }
        }

        // ---- unpack, mask, online softmax (rows shared across full warp) ----
        float sf[16][4];
#pragma unroll
        for (int p = 0; p < 8; p++)
#pragma unroll
            for (int jj = 0; jj < 4; jj++)
                upk2(s2[p][jj], sf[2 * p][jj], sf[2 * p + 1][jj]);

        const bool diag = (kt == qt_);
        float al[16];
#pragma unroll
        for (int i = 0; i < 16; ++i) {
            if (diag) {
#pragma unroll
                for (int jj = 0; jj < 4; ++jj)
                    if (4 * lane + jj > r0 + i) sf[i][jj] = -1e30f;
            }
            float mx = fmaxf(fmaxf(sf[i][0], sf[i][1]), fmaxf(sf[i][2], sf[i][3]));
#pragma unroll
            for (int off = 1; off < 32; off <<= 1)
                mx = fmaxf(mx, __shfl_xor_sync(0xffffffffu, mx, off));
            float mn = fmaxf(m_[i], mx);
            float sum = 0.0f;
#pragma unroll
            for (int jj = 0; jj < 4; ++jj) {
                float p = __expf(sf[i][jj] - mn);
                sf[i][jj] = p;
                sum += p;
            }
#pragma unroll
            for (int off = 1; off < 32; off <<= 1)
                sum += __shfl_xor_sync(0xffffffffu, sum, off);
            al[i] = __expf(m_[i] - mn);
            l_[i] = l_[i] * al[i] + sum;
            m_[i] = mn;
        }
#pragma unroll
        for (int p = 0; p < 8; ++p) {
            ull ap = pk2(al[2 * p], al[2 * p + 1]);
#pragma unroll
            for (int dd = 0; dd < 4; ++dd) mul2(o2[p][dd], ap);
        }
        __syncthreads();   // all warps done reading K before Pt overwrites it

        // ---- store Pt[j][r]: thread owns j-rows 4*lane..+3, r-chunks rq0..rq0+3 ----
#pragma unroll
        for (int jj = 0; jj < 4; ++jj) {
            const int prow = (4 * lane + jj) * 32;
#pragma unroll
            for (int cc = 0; cc < 4; ++cc) {
                KP4[prow + ((rq0 + cc) ^ sw8)] =
                    make_float4(sf[4 * cc + 0][jj], sf[4 * cc + 1][jj],
                                sf[4 * cc + 2][jj], sf[4 * cc + 3][jj]);
            }
        }
        __syncwarp();      // Pt r-columns produced & consumed within this warp only

        // ---- phase B: O += P @ V ; accum packed row-pairs ----
#pragma unroll 2
        for (int jc = 0; jc < 32; ++jc) {
            const int swv = jc & 7;
            float4 vf[4];
#pragma unroll
            for (int j4 = 0; j4 < 4; ++j4)
                vf[j4] = Vs4[(jc * 4 + j4) * 32 + (lane ^ swv)];
#pragma unroll
            for (int j4 = 0; j4 < 4; ++j4) {
                const int jrow = (jc * 4 + j4) * 32;
                ull pp[8];
#pragma unroll
                for (int cc = 0; cc < 4; ++cc) {
                    ulonglong2 t = KPl2[jrow + ((rq0 + cc) ^ swv)];
                    pp[2 * cc] = t.x; pp[2 * cc + 1] = t.y;
                }
#pragma unroll
                for (int dd = 0; dd < 4; ++dd) {
                    float vv = ((const float*)&vf[j4])[dd];
                    ull vd = pk2(vv, vv);
#pragma unroll
                    for (int p = 0; p < 8; ++p) fma2(o2[p][dd], pp[p], vd);
                }
            }
        }
        __syncthreads();   // before next tile overwrites KP/Vs
    }

    // ---- epilogue: normalize + store ctx (B,T,H,D); lanes contiguous in d ----
    const size_t obase = (((size_t)b * T_ + (size_t)qt_ * FT + r0) * H_ + h) * D_ + 4 * lane;
#pragma unroll
    for (int p = 0; p < 8; ++p) {
        float e0[4], e1[4];
#pragma unroll
        for (int dd = 0; dd < 4; ++dd) upk2(o2[p][dd], e0[dd], e1[dd]);
        float li0 = 1.0f / l_[2 * p];
        float li1 = 1.0f / l_[2 * p + 1];
        *(float4*)(ctx + obase + (size_t)(2 * p) * (H_ * D_)) =
            make_float4(e0[0] * li0, e0[1] * li0, e0[2] * li0, e0[3] * li0);
        *(float4*)(ctx + obase + (size_t)(2 * p + 1) * (H_ * D_)) =
            make_float4(e1[0] * li1, e1[1] * li1, e1[2] * li1, e1[3] * li1);
    }
}

// ---------------- launch ----------------
extern "C" void kernel_launch(void* const* d_in, const int* in_sizes, int n_in,
                              void* d_out, int out_size)
{
    const float* x  = (const float*)d_in[0];
    // d_in[1] = mask (int32 causal tril) — implied by flash kernel, unused
    const float* wq = (const float*)d_in[2];
    const float* wk = (const float*)d_in[3];
    const float* wv = (const float*)d_in[4];
    const float* wo = (const float*)d_in[5];
    float* out = (float*)d_out;

    float *gq, *gk, *gv, *gctx;
    cudaGetSymbolAddress((void**)&gq,   g_q);
    cudaGetSymbolAddress((void**)&gk,   g_k);
    cudaGetSymbolAddress((void**)&gv,   g_v);
    cudaGetSymbolAddress((void**)&gctx, g_ctx);

    const int M = B_ * T_;  // 4096

    rope_table_kernel<<<(T_ * 64) / 256, 256>>>();

    sgemm_kernel<<<dim3((H_ * D_) / 128, M / 128), 256>>>(x, wq, gq, M, H_ * D_, E_);
    sgemm_kernel<<<dim3((KVH_ * D_) / 128, M / 128), 256>>>(x, wk, gk, M, KVH_ * D_, E_);
    sgemm_kernel<<<dim3((KVH_ * D_) / 128, M / 128), 256>>>(x, wv, gv, M, KVH_ * D_, E_);

    int nq4 = B_ * T_ * H_ * (D_ / 4);
    int nk4 = B_ * T_ * KVH_ * (D_ / 4);
    rope_apply_kernel<<<nq4 / 256, 256>>>(gq, H_, nq4);
    rope_apply_kernel<<<nk4 / 256, 256>>>(gk, KVH_, nk4);

    cudaFuncSetAttribute(flash_kernel, cudaFuncAttributeMaxDynamicSharedMemorySize, FLASH_SMEM_BYTES);
    flash_kernel<<<dim3(T_ / FT, B_ * H_), 256, FLASH_SMEM_BYTES>>>(gq, gk, gv, gctx);

    sgemm_kernel<<<dim3(E_ / 128, M / 128), 256>>>(gctx, wo, out, M, E_, H_ * D_);
}

// round 12
// speedup vs baseline: 1.4529x; 1.4529x over previous
#include <cuda_runtime.h>
#include <cuda_bf16.h>
#include <math.h>

#define B_ 2
#define T_ 2048
#define E_ 2048
#define H_ 16
#define KVH_ 8
#define D_ 128
#define SCALE_ 0.08838834764831845f

typedef unsigned long long ull;
typedef unsigned int u32;

// ---------------- packed f32x2 helpers (flash kernel) ----------------
__device__ __forceinline__ ull pk2(float lo, float hi) {
    ull r; asm("mov.b64 %0, {%1, %2};" : "=l"(r) : "f"(lo), "f"(hi)); return r;
}
__device__ __forceinline__ void upk2(ull v, float& lo, float& hi) {
    asm("mov.b64 {%0, %1}, %2;" : "=f"(lo), "=f"(hi) : "l"(v));
}
__device__ __forceinline__ void fma2(ull& d, ull a, ull b) {
    asm("fma.rn.f32x2 %0, %1, %2, %0;" : "+l"(d) : "l"(a), "l"(b));
}
__device__ __forceinline__ void mul2(ull& d, ull a) {
    asm("mul.rn.f32x2 %0, %0, %1;" : "+l"(d) : "l"(a));
}

// ---------------- mma / ldmatrix wrappers ----------------
__device__ __forceinline__ u32 sm_u32(const void* p) {
    return (u32)__cvta_generic_to_shared(p);
}
__device__ __forceinline__ void ldsm4(u32* r, u32 addr) {
    asm volatile("ldmatrix.sync.aligned.m8n8.x4.shared.b16 {%0,%1,%2,%3}, [%4];"
                 : "=r"(r[0]), "=r"(r[1]), "=r"(r[2]), "=r"(r[3]) : "r"(addr));
}
__device__ __forceinline__ void ldsm4t(u32* r, u32 addr) {
    asm volatile("ldmatrix.sync.aligned.m8n8.x4.trans.shared.b16 {%0,%1,%2,%3}, [%4];"
                 : "=r"(r[0]), "=r"(r[1]), "=r"(r[2]), "=r"(r[3]) : "r"(addr));
}
__device__ __forceinline__ void mma_bf16(float* c, const u32* a, u32 b0, u32 b1) {
    asm volatile("mma.sync.aligned.m16n8k16.row.col.f32.bf16.bf16.f32 "
                 "{%0,%1,%2,%3}, {%4,%5,%6,%7}, {%8,%9}, {%0,%1,%2,%3};"
                 : "+f"(c[0]), "+f"(c[1]), "+f"(c[2]), "+f"(c[3])
                 : "r"(a[0]), "r"(a[1]), "r"(a[2]), "r"(a[3]), "r"(b0), "r"(b1));
}

// ---------------- scratch ----------------
__device__ float g_q[(size_t)B_ * T_ * H_ * D_];
__device__ float g_k[(size_t)B_ * T_ * KVH_ * D_];
__device__ float g_v[(size_t)B_ * T_ * KVH_ * D_];
__device__ float g_ctx[(size_t)B_ * T_ * H_ * D_];
__device__ float2 g_rope[T_ * 64];

// bf16 split scratch (stored as raw 16-bit halves)
__device__ unsigned short g_xhi[(size_t)B_ * T_ * E_];
__device__ unsigned short g_xlo[(size_t)B_ * T_ * E_];
__device__ unsigned short g_wqhi[(size_t)E_ * H_ * D_];
__device__ unsigned short g_wqlo[(size_t)E_ * H_ * D_];
__device__ unsigned short g_wkhi[(size_t)E_ * KVH_ * D_];
__device__ unsigned short g_wklo[(size_t)E_ * KVH_ * D_];
__device__ unsigned short g_wvhi[(size_t)E_ * KVH_ * D_];
__device__ unsigned short g_wvlo[(size_t)E_ * KVH_ * D_];
__device__ unsigned short g_wohi[(size_t)H_ * D_ * E_];
__device__ unsigned short g_wolo[(size_t)H_ * D_ * E_];
__device__ unsigned short g_chi[(size_t)B_ * T_ * H_ * D_];
__device__ unsigned short g_clo[(size_t)B_ * T_ * H_ * D_];

// ---------------- RoPE table ----------------
__global__ __launch_bounds__(256) void rope_table_kernel() {
    int idx = blockIdx.x * 256 + threadIdx.x;
    int t = idx >> 6, d2 = idx & 63;
    double inv = pow(10000.0, -(double)(2 * d2) / 128.0);
    double ang = (double)t * inv;
    g_rope[idx] = make_float2((float)cos(ang), (float)sin(ang));
}

// ---------------- RoPE apply ----------------
__global__ __launch_bounds__(256) void rope_apply_kernel(float* __restrict__ x, int heads, int total4) {
    int p = blockIdx.x * 256 + threadIdx.x;
    if (p >= total4) return;
    int cd = p & 31;
    int t = (p / (32 * heads)) % T_;
    float4 v = ((const float4*)x)[p];
    float2 r0 = g_rope[t * 64 + cd * 2];
    float2 r1 = g_rope[t * 64 + cd * 2 + 1];
    float a = v.x * r0.x - v.y * r0.y;
    float b = v.x * r0.y + v.y * r0.x;
    float c = v.z * r1.x - v.w * r1.y;
    float d = v.z * r1.y + v.w * r1.x;
    ((float4*)x)[p] = make_float4(a, b, c, d);
}

// round fp32 to bf16 bits (round-to-nearest-even), return as fp32 with low 16 bits zero
__device__ __forceinline__ float bf16_rnd(float x) {
    u32 u = __float_as_uint(x);
    u32 r = (u + 0x7fffu + ((u >> 16) & 1u)) & 0xffff0000u;
    return __uint_as_float(r);
}

// ---------------- split fp32 -> bf16 hi + bf16 lo (2 elems/thread) ----------------
__global__ __launch_bounds__(256) void split_kernel(
    const float* __restrict__ x, unsigned short* __restrict__ hi,
    unsigned short* __restrict__ lo, int n2)
{
    int i = blockIdx.x * 256 + threadIdx.x;
    if (i >= n2) return;
    float2 v = ((const float2*)x)[i];
    float hx = bf16_rnd(v.x);
    float hy = bf16_rnd(v.y);
    float lx = bf16_rnd(v.x - hx);
    float ly = bf16_rnd(v.y - hy);
    u32 hw = (__float_as_uint(hx) >> 16) | (__float_as_uint(hy) & 0xffff0000u);
    u32 lw = (__float_as_uint(lx) >> 16) | (__float_as_uint(ly) & 0xffff0000u);
    ((u32*)hi)[i] = hw;
    ((u32*)lo)[i] = lw;
}

// ---------------- bf16x3 split GEMM via mma.sync ----------------
// C (fp32) = Ahi*Bhi + Ahi*Blo + Alo*Bhi ; A,B row-major bf16 bits.
// CTA tile 128(M) x 64(N), k-chunk 32, 256 threads = 8 warps (2m x 4n), warp 64x16.
// Smem in uint4 units. A stage: 128 rows x 8 chunks (hi c0-3, lo c4-7), phys c ^ (row&7).
// B stage: 32 k-rows x 16 chunks (hi c0-7, lo c8-15), phys (within half) c ^ (krow&7).
#define GEMM_SMEM_BYTES (2 * (128 * 8 + 32 * 16) * 16)

__global__ __launch_bounds__(256, 2) void hgemm3_kernel(
    const unsigned short* __restrict__ Ahi, const unsigned short* __restrict__ Alo,
    const unsigned short* __restrict__ Bhi, const unsigned short* __restrict__ Blo,
    float* __restrict__ C, int M, int N, int K)
{
    extern __shared__ uint4 sg[];
    const int tid = threadIdx.x;
    const int lane = tid & 31, w = tid >> 5;
    const int wm = w >> 2, wn = w & 3;
    const int bx = blockIdx.x, by = blockIdx.y;

    const int ar = tid >> 1, ah = tid & 1;
    const int bkr = tid >> 3, bseg = tid & 7;

    const unsigned short* pAh = Ahi + (size_t)(by * 128 + ar) * K + ah * 16;
    const unsigned short* pAl = Alo + (size_t)(by * 128 + ar) * K + ah * 16;
    const unsigned short* pBh = Bhi + (size_t)bkr * N + bx * 64 + bseg * 8;
    const unsigned short* pBl = Blo + (size_t)bkr * N + bx * 64 + bseg * 8;

    const int sr7 = ar & 7;
    const int sA0 = ar * 8 + ((2 * ah + 0) ^ sr7);
    const int sA1 = ar * 8 + ((2 * ah + 1) ^ sr7);
    const int sA2 = ar * 8 + ((4 + 2 * ah) ^ sr7);
    const int sA3 = ar * 8 + ((5 + 2 * ah) ^ sr7);
    const int bk7 = bkr & 7;
    const int sB0 = bkr * 16 + (bseg ^ bk7);
    const int sB1 = bkr * 16 + 8 + (bseg ^ bk7);

    const int arow = wm * 64 + (lane & 7) + ((lane >> 3) & 1) * 8;
    const int ar7f = arow & 7;
    const int kbit = (lane >> 4) & 1;
    const int bkrS = (lane & 7) + ((lane >> 3) & 1) * 8;
    const int bcf = (wn * 2 + ((lane >> 4) & 1)) ^ (bkrS & 7);

    float acc[4][2][4];
#pragma unroll
    for (int mt = 0; mt < 4; mt++)
#pragma unroll
        for (int nt = 0; nt < 2; nt++)
#pragma unroll
            for (int e = 0; e < 4; e++) acc[mt][nt][e] = 0.0f;

    uint4 ra0, ra1, ra2, ra3, rb0, rb1;
    ra0 = *(const uint4*)pAh;  ra1 = *(const uint4*)(pAh + 8);
    ra2 = *(const uint4*)pAl;  ra3 = *(const uint4*)(pAl + 8);
    rb0 = *(const uint4*)pBh;  rb1 = *(const uint4*)pBl;
    sg[sA0] = ra0; sg[sA1] = ra1; sg[sA2] = ra2; sg[sA3] = ra3;
    sg[2048 + sB0] = rb0; sg[2048 + sB1] = rb1;
    __syncthreads();

    const int nch = K >> 5;
    for (int kc = 1; kc <= nch; ++kc) {
        if (kc < nch) {
            const unsigned short* a_h = pAh + kc * 32;
            const unsigned short* a_l = pAl + kc * 32;
            const unsigned short* b_h = pBh + (size_t)kc * 32 * N;
            const unsigned short* b_l = pBl + (size_t)kc * 32 * N;
            ra0 = *(const uint4*)a_h;  ra1 = *(const uint4*)(a_h + 8);
            ra2 = *(const uint4*)a_l;  ra3 = *(const uint4*)(a_l + 8);
            rb0 = *(const uint4*)b_h;  rb1 = *(const uint4*)b_l;
        }
        {
            const int st = (kc - 1) & 1;
            const uint4* smA = sg + st * 1024;
            const uint4* smB = sg + 2048 + st * 512;
#pragma unroll
            for (int s = 0; s < 2; ++s) {
                u32 afr[2][4][4];
#pragma unroll
                for (int sp = 0; sp < 2; ++sp)
#pragma unroll
                    for (int mt = 0; mt < 4; ++mt) {
                        int idx = (arow + 16 * mt) * 8 + ((2 * s + kbit + 4 * sp) ^ ar7f);
                        ldsm4(afr[sp][mt], sm_u32(smA + idx));
                    }
                u32 bfr[2][4];
#pragma unroll
                for (int sp = 0; sp < 2; ++sp) {
                    int idx = (bkrS + 16 * s) * 16 + sp * 8 + bcf;
                    ldsm4t(bfr[sp], sm_u32(smB + idx));
                }
#pragma unroll
                for (int mt = 0; mt < 4; ++mt)
#pragma unroll
                    for (int nt = 0; nt < 2; ++nt) {
                        mma_bf16(acc[mt][nt], afr[0][mt], bfr[0][2 * nt], bfr[0][2 * nt + 1]);
                        mma_bf16(acc[mt][nt], afr[0][mt], bfr[1][2 * nt], bfr[1][2 * nt + 1]);
                        mma_bf16(acc[mt][nt], afr[1][mt], bfr[0][2 * nt], bfr[0][2 * nt + 1]);
                    }
            }
        }
        if (kc < nch) {
            const int st = kc & 1;
            uint4* dA = sg + st * 1024;
            uint4* dB = sg + 2048 + st * 512;
            dA[sA0] = ra0; dA[sA1] = ra1; dA[sA2] = ra2; dA[sA3] = ra3;
            dB[sB0] = rb0; dB[sB1] = rb1;
            __syncthreads();
        }
    }

#pragma unroll
    for (int mt = 0; mt < 4; ++mt)
#pragma unroll
        for (int nt = 0; nt < 2; ++nt) {
            int gr = by * 128 + wm * 64 + mt * 16 + (lane >> 2);
            int gc = bx * 64 + wn * 16 + nt * 8 + (lane & 3) * 2;
            *(float2*)&C[(size_t)gr * N + gc] = make_float2(acc[mt][nt][0], acc[mt][nt][1]);
            *(float2*)&C[(size_t)(gr + 8) * N + gc] = make_float2(acc[mt][nt][2], acc[mt][nt][3]);
        }
}

// ---------------- Flash attention (round-7 best: 512 threads, FFMA2) ----------------
#define FT 128
#define FLASH_SMEM_BYTES (3 * 128 * 128 * 4)

__global__ __launch_bounds__(512) void flash_kernel(
    const float* __restrict__ q, const float* __restrict__ k,
    const float* __restrict__ v, float* __restrict__ ctx)
{
    extern __shared__ float sm[];
    float* Qt = sm;
    float* KP = sm + 16384;
    float* Vs = sm + 32768;

    const int qt_ = (int)gridDim.x - 1 - (int)blockIdx.x;
    const int bh = blockIdx.y;
    const int b = bh >> 4;
    const int h = bh & 15;
    const int g = h >> 1;
    const int tid = threadIdx.x;
    const int tx = tid & 31, ty = tid >> 5;
    const int r0 = ty * 8, c0 = tx * 4;

    const size_t qbase = (((size_t)b * T_ + (size_t)qt_ * FT) * H_ + h) * D_;
#pragma unroll
    for (int it = 0; it < 8; ++it) {
        int f = it * 512 + tid;
        int r = f >> 5, cd = f & 31;
        float4 val = *(const float4*)(q + qbase + (size_t)r * (H_ * D_) + cd * 4);
        val.x *= SCALE_; val.y *= SCALE_; val.z *= SCALE_; val.w *= SCALE_;
        int d0 = cd * 4;
        int rlow = r & 3, rch = r >> 2;
        Qt[(d0 + 0) * 128 + (((rch ^ (((d0 + 0) >> 3) & 7)) << 2) | rlow)] = val.x;
        Qt[(d0 + 1) * 128 + (((rch ^ (((d0 + 1) >> 3) & 7)) << 2) | rlow)] = val.y;
        Qt[(d0 + 2) * 128 + (((rch ^ (((d0 + 2) >> 3) & 7)) << 2) | rlow)] = val.z;
        Qt[(d0 + 3) * 128 + (((rch ^ (((d0 + 3) >> 3) & 7)) << 2) | rlow)] = val.w;
    }

    float m_[8], l_[8];
#pragma unroll
    for (int i = 0; i < 8; i++) { m_[i] = -1e30f; l_[i] = 0.0f; }

    ull o2[8][2];
#pragma unroll
    for (int i = 0; i < 8; i++) { o2[i][0] = 0ull; o2[i][1] = 0ull; }

    __syncthreads();

    for (int kt = 0; kt <= qt_; ++kt) {
        const size_t kvbase = (((size_t)b * T_ + (size_t)kt * FT) * KVH_ + g) * D_;
#pragma unroll
        for (int it = 0; it < 8; ++it) {
            int f = it * 512 + tid;
            int r = f >> 5, cd = f & 31;
            size_t off = kvbase + (size_t)r * (KVH_ * D_) + cd * 4;
            int sidx = r * 32 + (cd ^ ((r >> 2) & 7));
            ((float4*)KP)[sidx] = *(const float4*)(k + off);
            ((float4*)Vs)[sidx] = *(const float4*)(v + off);
        }
        __syncthreads();

        ull s2[4][4];
#pragma unroll
        for (int i = 0; i < 4; i++)
#pragma unroll
            for (int j = 0; j < 4; j++) s2[i][j] = 0ull;

#pragma unroll 4
        for (int kc = 0; kc < 32; ++kc) {
            float kf[4][4];
#pragma unroll
            for (int j = 0; j < 4; ++j) {
                int c = c0 + j;
                *(float4*)kf[j] = ((const float4*)KP)[c * 32 + (kc ^ ((c >> 2) & 7))];
            }
#pragma unroll
            for (int kk = 0; kk < 4; ++kk) {
                int kd = kc * 4 + kk;
                int s_ = (kd >> 3) & 7;
                ulonglong2 qa = ((const ulonglong2*)Qt)[kd * 32 + ((ty * 2) ^ s_)];
                ulonglong2 qb = ((const ulonglong2*)Qt)[kd * 32 + ((ty * 2 + 1) ^ s_)];
#pragma unroll
                for (int j = 0; j < 4; ++j) {
                    ull kdp = pk2(kf[j][kk], kf[j][kk]);
                    fma2(s2[0][j], qa.x, kdp);
                    fma2(s2[1][j], qa.y, kdp);
                    fma2(s2[2][j], qb.x, kdp);
                    fma2(s2[3][j], qb.y, kdp);
                }
            }
        }

        float sf[8][4];
#pragma unroll
        for (int p = 0; p < 4; p++)
#pragma unroll
            for (int j = 0; j < 4; j++)
                upk2(s2[p][j], sf[2 * p][j], sf[2 * p + 1][j]);

        const bool diag = (kt == qt_);
        float al_[8];
#pragma unroll
        for (int i = 0; i < 8; ++i) {
            if (diag) {
                int qi = qt_ * FT + r0 + i;
#pragma unroll
                for (int j = 0; j < 4; ++j)
                    if (kt * FT + c0 + j > qi) sf[i][j] = -1e30f;
            }
            float mx = fmaxf(fmaxf(sf[i][0], sf[i][1]), fmaxf(sf[i][2], sf[i][3]));
#pragma unroll
            for (int off = 1; off < 32; off <<= 1)
                mx = fmaxf(mx, __shfl_xor_sync(0xffffffffu, mx, off));
            float mn = fmaxf(m_[i], mx);
            float sum = 0.0f;
#pragma unroll
            for (int j = 0; j < 4; ++j) {
                float p = __expf(sf[i][j] - mn);
                sf[i][j] = p;
                sum += p;
            }
#pragma unroll
            for (int off = 1; off < 32; off <<= 1)
                sum += __shfl_xor_sync(0xffffffffu, sum, off);
            al_[i] = __expf(m_[i] - mn);
            l_[i] = l_[i] * al_[i] + sum;
            m_[i] = mn;
        }
        __syncthreads();

#pragma unroll
        for (int i = 0; i < 8; ++i) {
            int r = r0 + i;
            ((float4*)KP)[r * 32 + (tx ^ ((r >> 2) & 7))] =
                make_float4(sf[i][0], sf[i][1], sf[i][2], sf[i][3]);
        }
        __syncwarp();

#pragma unroll
        for (int i = 0; i < 8; ++i) {
            ull ap = pk2(al_[i], al_[i]);
            mul2(o2[i][0], ap);
            mul2(o2[i][1], ap);
        }

#pragma unroll 4
        for (int jc = 0; jc < 32; ++jc) {
            float pv[8][4];
#pragma unroll
            for (int i = 0; i < 8; ++i) {
                int r = r0 + i;
                *(float4*)pv[i] = ((const float4*)KP)[r * 32 + (jc ^ ((r >> 2) & 7))];
            }
            ull vv[4][2];
#pragma unroll
            for (int jj = 0; jj < 4; ++jj) {
                int r = jc * 4 + jj;
                ulonglong2 va = ((const ulonglong2*)Vs)[r * 32 + (tx ^ ((r >> 2) & 7))];
                vv[jj][0] = va.x; vv[jj][1] = va.y;
            }
#pragma unroll
            for (int jj = 0; jj < 4; ++jj)
#pragma unroll
                for (int i = 0; i < 8; ++i) {
                    ull pa = pk2(pv[i][jj], pv[i][jj]);
                    fma2(o2[i][0], pa, vv[jj][0]);
                    fma2(o2[i][1], pa, vv[jj][1]);
                }
        }
        __syncthreads();
    }

    const size_t obase = (((size_t)b * T_ + (size_t)qt_ * FT + r0) * H_ + h) * D_ + c0;
#pragma unroll
    for (int i = 0; i < 8; ++i) {
        float linv = 1.0f / l_[i];
        float of[4];
        upk2(o2[i][0], of[0], of[1]);
        upk2(o2[i][1], of[2], of[3]);
        *(float4*)(ctx + obase + (size_t)i * (H_ * D_)) =
            make_float4(of[0] * linv, of[1] * linv, of[2] * linv, of[3] * linv);
    }
}

// ---------------- launch ----------------
extern "C" void kernel_launch(void* const* d_in, const int* in_sizes, int n_in,
                              void* d_out, int out_size)
{
    const float* x  = (const float*)d_in[0];
    const float* wq = (const float*)d_in[2];
    const float* wk = (const float*)d_in[3];
    const float* wv = (const float*)d_in[4];
    const float* wo = (const float*)d_in[5];
    float* out = (float*)d_out;

    float *gq, *gk, *gv, *gctx;
    unsigned short *xhi, *xlo, *wqhi, *wqlo, *wkhi, *wklo, *wvhi, *wvlo, *wohi, *wolo, *chi, *clo;
    cudaGetSymbolAddress((void**)&gq,   g_q);
    cudaGetSymbolAddress((void**)&gk,   g_k);
    cudaGetSymbolAddress((void**)&gv,   g_v);
    cudaGetSymbolAddress((void**)&gctx, g_ctx);
    cudaGetSymbolAddress((void**)&xhi,  g_xhi);
    cudaGetSymbolAddress((void**)&xlo,  g_xlo);
    cudaGetSymbolAddress((void**)&wqhi, g_wqhi);
    cudaGetSymbolAddress((void**)&wqlo, g_wqlo);
    cudaGetSymbolAddress((void**)&wkhi, g_wkhi);
    cudaGetSymbolAddress((void**)&wklo, g_wklo);
    cudaGetSymbolAddress((void**)&wvhi, g_wvhi);
    cudaGetSymbolAddress((void**)&wvlo, g_wvlo);
    cudaGetSymbolAddress((void**)&wohi, g_wohi);
    cudaGetSymbolAddress((void**)&wolo, g_wolo);
    cudaGetSymbolAddress((void**)&chi,  g_chi);
    cudaGetSymbolAddress((void**)&clo,  g_clo);

    const int M = B_ * T_;
    const int HD = H_ * D_;
    const int KD = KVH_ * D_;

    cudaFuncSetAttribute(hgemm3_kernel, cudaFuncAttributeMaxDynamicSharedMemorySize, GEMM_SMEM_BYTES);
    cudaFuncSetAttribute(flash_kernel, cudaFuncAttributeMaxDynamicSharedMemorySize, FLASH_SMEM_BYTES);

    rope_table_kernel<<<(T_ * 64) / 256, 256>>>();

    split_kernel<<<(M * E_ / 2) / 256, 256>>>(x, xhi, xlo, M * E_ / 2);
    split_kernel<<<(E_ * HD / 2) / 256, 256>>>(wq, wqhi, wqlo, E_ * HD / 2);
    split_kernel<<<(E_ * KD / 2) / 256, 256>>>(wk, wkhi, wklo, E_ * KD / 2);
    split_kernel<<<(E_ * KD / 2) / 256, 256>>>(wv, wvhi, wvlo, E_ * KD / 2);
    split_kernel<<<(HD * E_ / 2) / 256, 256>>>(wo, wohi, wolo, HD * E_ / 2);

    hgemm3_kernel<<<dim3(HD / 64, M / 128), 256, GEMM_SMEM_BYTES>>>(xhi, xlo, wqhi, wqlo, gq, M, HD, E_);
    hgemm3_kernel<<<dim3(KD / 64, M / 128), 256, GEMM_SMEM_BYTES>>>(xhi, xlo, wkhi, wklo, gk, M, KD, E_);
    hgemm3_kernel<<<dim3(KD / 64, M / 128), 256, GEMM_SMEM_BYTES>>>(xhi, xlo, wvhi, wvlo, gv, M, KD, E_);

    int nq4 = B_ * T_ * H_ * (D_ / 4);
    int nk4 = B_ * T_ * KVH_ * (D_ / 4);
    rope_apply_kernel<<<nq4 / 256, 256>>>(gq, H_, nq4);
    rope_apply_kernel<<<nk4 / 256, 256>>>(gk, KVH_, nk4);

    flash_kernel<<<dim3(T_ / FT, B_ * H_), 512, FLASH_SMEM_BYTES>>>(gq, gk, gv, gctx);

    split_kernel<<<(M * HD / 2) / 256, 256>>>(gctx, chi, clo, M * HD / 2);
    hgemm3_kernel<<<dim3(E_ / 64, M / 128), 256, GEMM_SMEM_BYTES>>>(chi, clo, wohi, wolo, out, M, E_, HD);
}

// round 14
// speedup vs baseline: 2.0533x; 1.4132x over previous
#include <cuda_runtime.h>
#include <cuda_bf16.h>
#include <math.h>

#define B_ 2
#define T_ 2048
#define E_ 2048
#define H_ 16
#define KVH_ 8
#define D_ 128
#define SCALE_ 0.08838834764831845f

typedef unsigned long long ull;
typedef unsigned int u32;
typedef unsigned short u16;

// ---------------- mma / ldmatrix wrappers ----------------
__device__ __forceinline__ u32 sm_u32(const void* p) {
    return (u32)__cvta_generic_to_shared(p);
}
__device__ __forceinline__ void ldsm4(u32* r, u32 addr) {
    asm volatile("ldmatrix.sync.aligned.m8n8.x4.shared.b16 {%0,%1,%2,%3}, [%4];"
                 : "=r"(r[0]), "=r"(r[1]), "=r"(r[2]), "=r"(r[3]) : "r"(addr));
}
__device__ __forceinline__ void ldsm4t(u32* r, u32 addr) {
    asm volatile("ldmatrix.sync.aligned.m8n8.x4.trans.shared.b16 {%0,%1,%2,%3}, [%4];"
                 : "=r"(r[0]), "=r"(r[1]), "=r"(r[2]), "=r"(r[3]) : "r"(addr));
}
__device__ __forceinline__ void mma_bf16(float* c, const u32* a, u32 b0, u32 b1) {
    asm volatile("mma.sync.aligned.m16n8k16.row.col.f32.bf16.bf16.f32 "
                 "{%0,%1,%2,%3}, {%4,%5,%6,%7}, {%8,%9}, {%0,%1,%2,%3};"
                 : "+f"(c[0]), "+f"(c[1]), "+f"(c[2]), "+f"(c[3])
                 : "r"(a[0]), "r"(a[1]), "r"(a[2]), "r"(a[3]), "r"(b0), "r"(b1));
}
// pack two fp32 into bf16x2: element0(low16)=lo, element1(high16)=hi
__device__ __forceinline__ u32 mk_bf2(float lo, float hi) {
    u32 r;
    asm("cvt.rn.bf16x2.f32 %0, %1, %2;" : "=r"(r) : "f"(hi), "f"(lo));
    return r;
}

// ---------------- scratch ----------------
__device__ float g_q[(size_t)B_ * T_ * H_ * D_];
__device__ float g_k[(size_t)B_ * T_ * KVH_ * D_];
__device__ float g_v[(size_t)B_ * T_ * KVH_ * D_];
__device__ float g_ctx[(size_t)B_ * T_ * H_ * D_];
__device__ float2 g_rope[T_ * 64];

__device__ u16 g_xhi[(size_t)B_ * T_ * E_];
__device__ u16 g_xlo[(size_t)B_ * T_ * E_];
__device__ u16 g_wqhi[(size_t)E_ * H_ * D_];
__device__ u16 g_wqlo[(size_t)E_ * H_ * D_];
__device__ u16 g_wkhi[(size_t)E_ * KVH_ * D_];
__device__ u16 g_wklo[(size_t)E_ * KVH_ * D_];
__device__ u16 g_wvhi[(size_t)E_ * KVH_ * D_];
__device__ u16 g_wvlo[(size_t)E_ * KVH_ * D_];
__device__ u16 g_wohi[(size_t)H_ * D_ * E_];
__device__ u16 g_wolo[(size_t)H_ * D_ * E_];
__device__ u16 g_chi[(size_t)B_ * T_ * H_ * D_];
__device__ u16 g_clo[(size_t)B_ * T_ * H_ * D_];

// ---------------- RoPE ----------------
__global__ __launch_bounds__(256) void rope_table_kernel() {
    int idx = blockIdx.x * 256 + threadIdx.x;
    int t = idx >> 6, d2 = idx & 63;
    double inv = pow(10000.0, -(double)(2 * d2) / 128.0);
    double ang = (double)t * inv;
    g_rope[idx] = make_float2((float)cos(ang), (float)sin(ang));
}

__global__ __launch_bounds__(256) void rope_apply_kernel(float* __restrict__ x, int heads, int total4) {
    int p = blockIdx.x * 256 + threadIdx.x;
    if (p >= total4) return;
    int cd = p & 31;
    int t = (p / (32 * heads)) % T_;
    float4 v = ((const float4*)x)[p];
    float2 r0 = g_rope[t * 64 + cd * 2];
    float2 r1 = g_rope[t * 64 + cd * 2 + 1];
    float a = v.x * r0.x - v.y * r0.y;
    float b = v.x * r0.y + v.y * r0.x;
    float c = v.z * r1.x - v.w * r1.y;
    float d = v.z * r1.y + v.w * r1.x;
    ((float4*)x)[p] = make_float4(a, b, c, d);
}

__device__ __forceinline__ float bf16_rnd(float x) {
    u32 u = __float_as_uint(x);
    u32 r = (u + 0x7fffu + ((u >> 16) & 1u)) & 0xffff0000u;
    return __uint_as_float(r);
}

// ---------------- split fp32 -> bf16 hi + lo ----------------
__global__ __launch_bounds__(256) void split_kernel(
    const float* __restrict__ x, u16* __restrict__ hi, u16* __restrict__ lo, int n2)
{
    int i = blockIdx.x * 256 + threadIdx.x;
    if (i >= n2) return;
    float2 v = ((const float2*)x)[i];
    float hx = bf16_rnd(v.x);
    float hy = bf16_rnd(v.y);
    float lx = bf16_rnd(v.x - hx);
    float ly = bf16_rnd(v.y - hy);
    u32 hw = (__float_as_uint(hx) >> 16) | (__float_as_uint(hy) & 0xffff0000u);
    u32 lw = (__float_as_uint(lx) >> 16) | (__float_as_uint(ly) & 0xffff0000u);
    ((u32*)hi)[i] = hw;
    ((u32*)lo)[i] = lw;
}

// ---------------- bf16x3 split GEMM via mma.sync (round-12, passing) ----------------
#define GEMM_SMEM_BYTES (2 * (128 * 8 + 32 * 16) * 16)

__global__ __launch_bounds__(256, 2) void hgemm3_kernel(
    const u16* __restrict__ Ahi, const u16* __restrict__ Alo,
    const u16* __restrict__ Bhi, const u16* __restrict__ Blo,
    float* __restrict__ C, int M, int N, int K)
{
    extern __shared__ uint4 sg[];
    const int tid = threadIdx.x;
    const int lane = tid & 31, w = tid >> 5;
    const int wm = w >> 2, wn = w & 3;
    const int bx = blockIdx.x, by = blockIdx.y;

    const int ar = tid >> 1, ah = tid & 1;
    const int bkr = tid >> 3, bseg = tid & 7;

    const u16* pAh = Ahi + (size_t)(by * 128 + ar) * K + ah * 16;
    const u16* pAl = Alo + (size_t)(by * 128 + ar) * K + ah * 16;
    const u16* pBh = Bhi + (size_t)bkr * N + bx * 64 + bseg * 8;
    const u16* pBl = Blo + (size_t)bkr * N + bx * 64 + bseg * 8;

    const int sr7 = ar & 7;
    const int sA0 = ar * 8 + ((2 * ah + 0) ^ sr7);
    const int sA1 = ar * 8 + ((2 * ah + 1) ^ sr7);
    const int sA2 = ar * 8 + ((4 + 2 * ah) ^ sr7);
    const int sA3 = ar * 8 + ((5 + 2 * ah) ^ sr7);
    const int bk7 = bkr & 7;
    const int sB0 = bkr * 16 + (bseg ^ bk7);
    const int sB1 = bkr * 16 + 8 + (bseg ^ bk7);

    const int arow = wm * 64 + (lane & 7) + ((lane >> 3) & 1) * 8;
    const int ar7f = arow & 7;
    const int kbit = (lane >> 4) & 1;
    const int bkrS = (lane & 7) + ((lane >> 3) & 1) * 8;
    const int bcf = (wn * 2 + ((lane >> 4) & 1)) ^ (bkrS & 7);

    float acc[4][2][4];
#pragma unroll
    for (int mt = 0; mt < 4; mt++)
#pragma unroll
        for (int nt = 0; nt < 2; nt++)
#pragma unroll
            for (int e = 0; e < 4; e++) acc[mt][nt][e] = 0.0f;

    uint4 ra0, ra1, ra2, ra3, rb0, rb1;
    ra0 = *(const uint4*)pAh;  ra1 = *(const uint4*)(pAh + 8);
    ra2 = *(const uint4*)pAl;  ra3 = *(const uint4*)(pAl + 8);
    rb0 = *(const uint4*)pBh;  rb1 = *(const uint4*)pBl;
    sg[sA0] = ra0; sg[sA1] = ra1; sg[sA2] = ra2; sg[sA3] = ra3;
    sg[2048 + sB0] = rb0; sg[2048 + sB1] = rb1;
    __syncthreads();

    const int nch = K >> 5;
    for (int kc = 1; kc <= nch; ++kc) {
        if (kc < nch) {
            const u16* a_h = pAh + kc * 32;
            const u16* a_l = pAl + kc * 32;
            const u16* b_h = pBh + (size_t)kc * 32 * N;
            const u16* b_l = pBl + (size_t)kc * 32 * N;
            ra0 = *(const uint4*)a_h;  ra1 = *(const uint4*)(a_h + 8);
            ra2 = *(const uint4*)a_l;  ra3 = *(const uint4*)(a_l + 8);
            rb0 = *(const uint4*)b_h;  rb1 = *(const uint4*)b_l;
        }
        {
            const int st = (kc - 1) & 1;
            const uint4* smA = sg + st * 1024;
            const uint4* smB = sg + 2048 + st * 512;
#pragma unroll
            for (int s = 0; s < 2; ++s) {
                u32 afr[2][4][4];
#pragma unroll
                for (int sp = 0; sp < 2; ++sp)
#pragma unroll
                    for (int mt = 0; mt < 4; ++mt) {
                        int idx = (arow + 16 * mt) * 8 + ((2 * s + kbit + 4 * sp) ^ ar7f);
                        ldsm4(afr[sp][mt], sm_u32(smA + idx));
                    }
                u32 bfr[2][4];
#pragma unroll
                for (int sp = 0; sp < 2; ++sp) {
                    int idx = (bkrS + 16 * s) * 16 + sp * 8 + bcf;
                    ldsm4t(bfr[sp], sm_u32(smB + idx));
                }
#pragma unroll
                for (int mt = 0; mt < 4; ++mt)
#pragma unroll
                    for (int nt = 0; nt < 2; ++nt) {
                        mma_bf16(acc[mt][nt], afr[0][mt], bfr[0][2 * nt], bfr[0][2 * nt + 1]);
                        mma_bf16(acc[mt][nt], afr[0][mt], bfr[1][2 * nt], bfr[1][2 * nt + 1]);
                        mma_bf16(acc[mt][nt], afr[1][mt], bfr[0][2 * nt], bfr[0][2 * nt + 1]);
                    }
            }
        }
        if (kc < nch) {
            const int st = kc & 1;
            uint4* dA = sg + st * 1024;
            uint4* dB = sg + 2048 + st * 512;
            dA[sA0] = ra0; dA[sA1] = ra1; dA[sA2] = ra2; dA[sA3] = ra3;
            dB[sB0] = rb0; dB[sB1] = rb1;
            __syncthreads();
        }
    }

#pragma unroll
    for (int mt = 0; mt < 4; ++mt)
#pragma unroll
        for (int nt = 0; nt < 2; ++nt) {
            int gr = by * 128 + wm * 64 + mt * 16 + (lane >> 2);
            int gc = bx * 64 + wn * 16 + nt * 8 + (lane & 3) * 2;
            *(float2*)&C[(size_t)gr * N + gc] = make_float2(acc[mt][nt][0], acc[mt][nt][1]);
            *(float2*)&C[(size_t)(gr + 8) * N + gc] = make_float2(acc[mt][nt][2], acc[mt][nt][3]);
        }
}

// ---------------- Flash attention on mma.sync (bf16x3) ----------------
// 256 threads, 8 warps; warp w owns q-rows 16w..16w+15. qtile=kvtile=128.
// Smem: Qhi/Qlo/Khi/Klo/Vhi/Vlo, each 128x128 bf16 (32KB) = 192KB.
// Tile layout: row r = 128 bf16 = 16 uint4 chunks, phys chunk = c ^ (r & 7).
// Phase A: S = Q*K^T. A-frag: non-trans ldsm on Q rows. B-frag: non-trans ldsm
//   on K rows (K[kv][d] is col-major B); n8 tile 2g uses regs {0,2}, 2g+1 {1,3}.
// Softmax on C fragments (row = lane>>2 / +8, quad shuffle reduce).
// Phase B: O += P*V. A-frag built in regs from exp'd S (C layout == A layout, n<->k),
//   packed to bf16 hi/lo. B-frag: trans ldsm on V rows; d-tile 2g regs {0,1}, 2g+1 {2,3}.
#define FSM_BYTES 196608

__device__ __forceinline__ u32 tile_addr(u32 base, int row, int chunk) {
    return base + (u32)(((row << 4) + (chunk ^ (row & 7))) << 4);
}

__global__ __launch_bounds__(256) void flashmma_kernel(
    const float* __restrict__ q, const float* __restrict__ k,
    const float* __restrict__ v, float* __restrict__ ctx)
{
    extern __shared__ char fsm[];
    uint4* Q4hi = (uint4*)fsm;
    uint4* Q4lo = (uint4*)(fsm + 32768);
    uint4* K4hi = (uint4*)(fsm + 65536);
    uint4* K4lo = (uint4*)(fsm + 98304);
    uint4* V4hi = (uint4*)(fsm + 131072);
    uint4* V4lo = (uint4*)(fsm + 163840);
    const u32 uQhi = sm_u32(Q4hi), uQlo = sm_u32(Q4lo);
    const u32 uKhi = sm_u32(K4hi), uKlo = sm_u32(K4lo);
    const u32 uVhi = sm_u32(V4hi), uVlo = sm_u32(V4lo);

    const int qt_ = (int)gridDim.x - 1 - (int)blockIdx.x;
    const int bh = blockIdx.y;
    const int b = bh >> 4;
    const int h = bh & 15;
    const int g = h >> 1;
    const int tid = threadIdx.x;
    const int lane = tid & 31, wid = tid >> 5;
    const int m0 = wid * 16;

    // ---- load Q (scaled), split to bf16 hi/lo tiles ----
    const size_t qbase = (((size_t)b * T_ + (size_t)qt_ * 128) * H_ + h) * D_;
#pragma unroll
    for (int it = 0; it < 8; ++it) {
        int f = it * 256 + tid;
        int r = f >> 4, c = f & 15;
        const float* src = q + qbase + (size_t)r * (H_ * D_) + c * 8;
        float4 a = *(const float4*)src;
        float4 bb = *(const float4*)(src + 4);
        float vals[8] = {a.x, a.y, a.z, a.w, bb.x, bb.y, bb.z, bb.w};
        u32 hw[4], lw[4];
#pragma unroll
        for (int j = 0; j < 4; ++j) {
            float v0 = vals[2 * j] * SCALE_, v1 = vals[2 * j + 1] * SCALE_;
            float h0 = bf16_rnd(v0), h1 = bf16_rnd(v1);
            float l0 = bf16_rnd(v0 - h0), l1 = bf16_rnd(v1 - h1);
            hw[j] = (__float_as_uint(h0) >> 16) | (__float_as_uint(h1) & 0xffff0000u);
            lw[j] = (__float_as_uint(l0) >> 16) | (__float_as_uint(l1) & 0xffff0000u);
        }
        int idx = r * 16 + (c ^ (r & 7));
        Q4hi[idx] = make_uint4(hw[0], hw[1], hw[2], hw[3]);
        Q4lo[idx] = make_uint4(lw[0], lw[1], lw[2], lw[3]);
    }

    float oc[16][4];
#pragma unroll
    for (int t = 0; t < 16; ++t)
#pragma unroll
        for (int e = 0; e < 4; ++e) oc[t][e] = 0.0f;
    float mA = -1e30f, mB = -1e30f, lA = 0.0f, lB = 0.0f;

    __syncthreads();

    for (int kt = 0; kt <= qt_; ++kt) {
        // ---- load K,V tiles, split ----
        const size_t kvbase = (((size_t)b * T_ + (size_t)kt * 128) * KVH_ + g) * D_;
#pragma unroll
        for (int it = 0; it < 8; ++it) {
            int f = it * 256 + tid;
            int r = f >> 4, c = f & 15;
            const float* ks = k + kvbase + (size_t)r * (KVH_ * D_) + c * 8;
            const float* vs = v + kvbase + (size_t)r * (KVH_ * D_) + c * 8;
            float4 ka = *(const float4*)ks;
            float4 kb = *(const float4*)(ks + 4);
            float4 va = *(const float4*)vs;
            float4 vb = *(const float4*)(vs + 4);
            float kv8[8] = {ka.x, ka.y, ka.z, ka.w, kb.x, kb.y, kb.z, kb.w};
            float vv8[8] = {va.x, va.y, va.z, va.w, vb.x, vb.y, vb.z, vb.w};
            u32 khw[4], klw[4], vhw[4], vlw[4];
#pragma unroll
            for (int j = 0; j < 4; ++j) {
                float k0 = kv8[2 * j], k1 = kv8[2 * j + 1];
                float kh0 = bf16_rnd(k0), kh1 = bf16_rnd(k1);
                float kl0 = bf16_rnd(k0 - kh0), kl1 = bf16_rnd(k1 - kh1);
                khw[j] = (__float_as_uint(kh0) >> 16) | (__float_as_uint(kh1) & 0xffff0000u);
                klw[j] = (__float_as_uint(kl0) >> 16) | (__float_as_uint(kl1) & 0xffff0000u);
                float w0 = vv8[2 * j], w1 = vv8[2 * j + 1];
                float vh0 = bf16_rnd(w0), vh1 = bf16_rnd(w1);
                float vl0 = bf16_rnd(w0 - vh0), vl1 = bf16_rnd(w1 - vh1);
                vhw[j] = (__float_as_uint(vh0) >> 16) | (__float_as_uint(vh1) & 0xffff0000u);
                vlw[j] = (__float_as_uint(vl0) >> 16) | (__float_as_uint(vl1) & 0xffff0000u);
            }
            int idx = r * 16 + (c ^ (r & 7));
            K4hi[idx] = make_uint4(khw[0], khw[1], khw[2], khw[3]);
            K4lo[idx] = make_uint4(klw[0], klw[1], klw[2], klw[3]);
            V4hi[idx] = make_uint4(vhw[0], vhw[1], vhw[2], vhw[3]);
            V4lo[idx] = make_uint4(vlw[0], vlw[1], vlw[2], vlw[3]);
        }
        __syncthreads();

        // ---- phase A: S = Q K^T (bf16x3) ----
        float sc[16][4];
#pragma unroll
        for (int t = 0; t < 16; ++t)
#pragma unroll
            for (int e = 0; e < 4; ++e) sc[t][e] = 0.0f;

#pragma unroll
        for (int kt16 = 0; kt16 < 8; ++kt16) {
            const int arow = m0 + (lane & 15);
            const int ac = 2 * kt16 + (lane >> 4);
            u32 ah[4], al[4];
            ldsm4(ah, tile_addr(uQhi, arow, ac));
            ldsm4(al, tile_addr(uQlo, arow, ac));
#pragma unroll
            for (int gg = 0; gg < 8; ++gg) {
                const int brow = gg * 16 + (lane & 15);
                u32 kh[4], kl[4];
                ldsm4(kh, tile_addr(uKhi, brow, ac));
                ldsm4(kl, tile_addr(uKlo, brow, ac));
                mma_bf16(sc[2 * gg], ah, kh[0], kh[2]);
                mma_bf16(sc[2 * gg], ah, kl[0], kl[2]);
                mma_bf16(sc[2 * gg], al, kh[0], kh[2]);
                mma_bf16(sc[2 * gg + 1], ah, kh[1], kh[3]);
                mma_bf16(sc[2 * gg + 1], ah, kl[1], kl[3]);
                mma_bf16(sc[2 * gg + 1], al, kh[1], kh[3]);
            }
        }

        // ---- mask (diag tile) ----
        if (kt == qt_) {
            int rl = m0 + (lane >> 2);
#pragma unroll
            for (int t = 0; t < 16; ++t) {
                int c0 = t * 8 + 2 * (lane & 3);
                if (c0 > rl)     sc[t][0] = -1e30f;
                if (c0 + 1 > rl) sc[t][1] = -1e30f;
                if (c0 > rl + 8)     sc[t][2] = -1e30f;
                if (c0 + 1 > rl + 8) sc[t][3] = -1e30f;
            }
        }

        // ---- online softmax on fragments ----
        {
            float mxA = -1e30f, mxB = -1e30f;
#pragma unroll
            for (int t = 0; t < 16; ++t) {
                mxA = fmaxf(mxA, fmaxf(sc[t][0], sc[t][1]));
                mxB = fmaxf(mxB, fmaxf(sc[t][2], sc[t][3]));
            }
            mxA = fmaxf(mxA, __shfl_xor_sync(0xffffffffu, mxA, 1));
            mxA = fmaxf(mxA, __shfl_xor_sync(0xffffffffu, mxA, 2));
            mxB = fmaxf(mxB, __shfl_xor_sync(0xffffffffu, mxB, 1));
            mxB = fmaxf(mxB, __shfl_xor_sync(0xffffffffu, mxB, 2));
            float mnA = fmaxf(mA, mxA), mnB = fmaxf(mB, mxB);
            float sA = 0.0f, sB = 0.0f;
#pragma unroll
            for (int t = 0; t < 16; ++t) {
                sc[t][0] = __expf(sc[t][0] - mnA);
                sc[t][1] = __expf(sc[t][1] - mnA);
                sc[t][2] = __expf(sc[t][2] - mnB);
                sc[t][3] = __expf(sc[t][3] - mnB);
                sA += sc[t][0] + sc[t][1];
                sB += sc[t][2] + sc[t][3];
            }
            sA += __shfl_xor_sync(0xffffffffu, sA, 1);
            sA += __shfl_xor_sync(0xffffffffu, sA, 2);
            sB += __shfl_xor_sync(0xffffffffu, sB, 1);
            sB += __shfl_xor_sync(0xffffffffu, sB, 2);
            float alA = __expf(mA - mnA), alB = __expf(mB - mnB);
            lA = lA * alA + sA;  mA = mnA;
            lB = lB * alB + sB;  mB = mnB;
#pragma unroll
            for (int t = 0; t < 16; ++t) {
                oc[t][0] *= alA; oc[t][1] *= alA;
                oc[t][2] *= alB; oc[t][3] *= alB;
            }
        }

        // ---- phase B: O += P V (bf16x3, P from registers) ----
#pragma unroll
        for (int kt2 = 0; kt2 < 8; ++kt2) {
            u32 pah[4], pal[4];
#pragma unroll
            for (int j = 0; j < 4; ++j) {
                int t = 2 * kt2 + (j >> 1);
                int e = (j & 1) * 2;
                float p0 = sc[t][e], p1 = sc[t][e + 1];
                u32 hp = mk_bf2(p0, p1);
                float r0 = p0 - __uint_as_float(hp << 16);
                float r1 = p1 - __uint_as_float(hp & 0xffff0000u);
                pah[j] = hp;
                pal[j] = mk_bf2(r0, r1);
            }
#pragma unroll
            for (int gg = 0; gg < 8; ++gg) {
                const int vrow = kt2 * 16 + (lane & 15);
                const int vc = 2 * gg + (lane >> 4);
                u32 vh[4], vl[4];
                ldsm4t(vh, tile_addr(uVhi, vrow, vc));
                ldsm4t(vl, tile_addr(uVlo, vrow, vc));
                mma_bf16(oc[2 * gg], pah, vh[0], vh[1]);
                mma_bf16(oc[2 * gg], pah, vl[0], vl[1]);
                mma_bf16(oc[2 * gg], pal, vh[0], vh[1]);
                mma_bf16(oc[2 * gg + 1], pah, vh[2], vh[3]);
                mma_bf16(oc[2 * gg + 1], pah, vl[2], vl[3]);
                mma_bf16(oc[2 * gg + 1], pal, vh[2], vh[3]);
            }
        }
        __syncthreads();
    }

    // ---- epilogue ----
    {
        float iA = 1.0f / lA, iB = 1.0f / lB;
        int rA = qt_ * 128 + m0 + (lane >> 2);
        int rB = rA + 8;
        size_t baseA = (((size_t)b * T_ + rA) * H_ + h) * D_;
        size_t baseB = (((size_t)b * T_ + rB) * H_ + h) * D_;
        int cb = 2 * (lane & 3);
#pragma unroll
        for (int t = 0; t < 16; ++t) {
            int col = t * 8 + cb;
            *(float2*)&ctx[baseA + col] = make_float2(oc[t][0] * iA, oc[t][1] * iA);
            *(float2*)&ctx[baseB + col] = make_float2(oc[t][2] * iB, oc[t][3] * iB);
        }
    }
}

// ---------------- launch ----------------
extern "C" void kernel_launch(void* const* d_in, const int* in_sizes, int n_in,
                              void* d_out, int out_size)
{
    const float* x  = (const float*)d_in[0];
    const float* wq = (const float*)d_in[2];
    const float* wk = (const float*)d_in[3];
    const float* wv = (const float*)d_in[4];
    const float* wo = (const float*)d_in[5];
    float* out = (float*)d_out;

    float *gq, *gk, *gv, *gctx;
    u16 *xhi, *xlo, *wqhi, *wqlo, *wkhi, *wklo, *wvhi, *wvlo, *wohi, *wolo, *chi, *clo;
    cudaGetSymbolAddress((void**)&gq,   g_q);
    cudaGetSymbolAddress((void**)&gk,   g_k);
    cudaGetSymbolAddress((void**)&gv,   g_v);
    cudaGetSymbolAddress((void**)&gctx, g_ctx);
    cudaGetSymbolAddress((void**)&xhi,  g_xhi);
    cudaGetSymbolAddress((void**)&xlo,  g_xlo);
    cudaGetSymbolAddress((void**)&wqhi, g_wqhi);
    cudaGetSymbolAddress((void**)&wqlo, g_wqlo);
    cudaGetSymbolAddress((void**)&wkhi, g_wkhi);
    cudaGetSymbolAddress((void**)&wklo, g_wklo);
    cudaGetSymbolAddress((void**)&wvhi, g_wvhi);
    cudaGetSymbolAddress((void**)&wvlo, g_wvlo);
    cudaGetSymbolAddress((void**)&wohi, g_wohi);
    cudaGetSymbolAddress((void**)&wolo, g_wolo);
    cudaGetSymbolAddress((void**)&chi,  g_chi);
    cudaGetSymbolAddress((void**)&clo,  g_clo);

    const int M = B_ * T_;
    const int HD = H_ * D_;
    const int KD = KVH_ * D_;

    cudaFuncSetAttribute(hgemm3_kernel, cudaFuncAttributeMaxDynamicSharedMemorySize, GEMM_SMEM_BYTES);
    cudaFuncSetAttribute(flashmma_kernel, cudaFuncAttributeMaxDynamicSharedMemorySize, FSM_BYTES);

    rope_table_kernel<<<(T_ * 64) / 256, 256>>>();

    split_kernel<<<(M * E_ / 2) / 256, 256>>>(x, xhi, xlo, M * E_ / 2);
    split_kernel<<<(E_ * HD / 2) / 256, 256>>>(wq, wqhi, wqlo, E_ * HD / 2);
    split_kernel<<<(E_ * KD / 2) / 256, 256>>>(wk, wkhi, wklo, E_ * KD / 2);
    split_kernel<<<(E_ * KD / 2) / 256, 256>>>(wv, wvhi, wvlo, E_ * KD / 2);
    split_kernel<<<(HD * E_ / 2) / 256, 256>>>(wo, wohi, wolo, HD * E_ / 2);

    hgemm3_kernel<<<dim3(HD / 64, M / 128), 256, GEMM_SMEM_BYTES>>>(xhi, xlo, wqhi, wqlo, gq, M, HD, E_);
    hgemm3_kernel<<<dim3(KD / 64, M / 128), 256, GEMM_SMEM_BYTES>>>(xhi, xlo, wkhi, wklo, gk, M, KD, E_);
    hgemm3_kernel<<<dim3(KD / 64, M / 128), 256, GEMM_SMEM_BYTES>>>(xhi, xlo, wvhi, wvlo, gv, M, KD, E_);

    int nq4 = B_ * T_ * H_ * (D_ / 4);
    int nk4 = B_ * T_ * KVH_ * (D_ / 4);
    rope_apply_kernel<<<nq4 / 256, 256>>>(gq, H_, nq4);
    rope_apply_kernel<<<nk4 / 256, 256>>>(gk, KVH_, nk4);

    flashmma_kernel<<<dim3(T_ / 128, B_ * H_), 256, FSM_BYTES>>>(gq, gk, gv, gctx);

    split_kernel<<<(M * HD / 2) / 256, 256>>>(gctx, chi, clo, M * HD / 2);
    hgemm3_kernel<<<dim3(E_ / 64, M / 128), 256, GEMM_SMEM_BYTES>>>(chi, clo, wohi, wolo, out, M, E_, HD);
}

// round 15
// speedup vs baseline: 2.4809x; 1.2083x over previous
#include <cuda_runtime.h>
#include <cuda_bf16.h>
#include <math.h>

#define B_ 2
#define T_ 2048
#define E_ 2048
#define H_ 16
#define KVH_ 8
#define D_ 128
#define SCALE_ 0.08838834764831845f

typedef unsigned long long ull;
typedef unsigned int u32;
typedef unsigned short u16;

// ---------------- mma / ldmatrix wrappers ----------------
__device__ __forceinline__ u32 sm_u32(const void* p) {
    return (u32)__cvta_generic_to_shared(p);
}
__device__ __forceinline__ void ldsm4(u32* r, u32 addr) {
    asm volatile("ldmatrix.sync.aligned.m8n8.x4.shared.b16 {%0,%1,%2,%3}, [%4];"
                 : "=r"(r[0]), "=r"(r[1]), "=r"(r[2]), "=r"(r[3]) : "r"(addr));
}
__device__ __forceinline__ void ldsm4t(u32* r, u32 addr) {
    asm volatile("ldmatrix.sync.aligned.m8n8.x4.trans.shared.b16 {%0,%1,%2,%3}, [%4];"
                 : "=r"(r[0]), "=r"(r[1]), "=r"(r[2]), "=r"(r[3]) : "r"(addr));
}
__device__ __forceinline__ void mma_bf16(float* c, const u32* a, u32 b0, u32 b1) {
    asm volatile("mma.sync.aligned.m16n8k16.row.col.f32.bf16.bf16.f32 "
                 "{%0,%1,%2,%3}, {%4,%5,%6,%7}, {%8,%9}, {%0,%1,%2,%3};"
                 : "+f"(c[0]), "+f"(c[1]), "+f"(c[2]), "+f"(c[3])
                 : "r"(a[0]), "r"(a[1]), "r"(a[2]), "r"(a[3]), "r"(b0), "r"(b1));
}
__device__ __forceinline__ u32 mk_bf2(float lo, float hi) {
    u32 r;
    asm("cvt.rn.bf16x2.f32 %0, %1, %2;" : "=r"(r) : "f"(hi), "f"(lo));
    return r;
}

// ---------------- scratch ----------------
__device__ float g_q[(size_t)B_ * T_ * H_ * D_];
__device__ float g_k[(size_t)B_ * T_ * KVH_ * D_];
__device__ float g_v[(size_t)B_ * T_ * KVH_ * D_];
__device__ float g_ctx[(size_t)B_ * T_ * H_ * D_];
__device__ float2 g_rope[T_ * 64];

__device__ u16 g_xhi[(size_t)B_ * T_ * E_];
__device__ u16 g_xlo[(size_t)B_ * T_ * E_];
__device__ u16 g_wqhi[(size_t)E_ * H_ * D_];
__device__ u16 g_wqlo[(size_t)E_ * H_ * D_];
__device__ u16 g_wkhi[(size_t)E_ * KVH_ * D_];
__device__ u16 g_wklo[(size_t)E_ * KVH_ * D_];
__device__ u16 g_wvhi[(size_t)E_ * KVH_ * D_];
__device__ u16 g_wvlo[(size_t)E_ * KVH_ * D_];
__device__ u16 g_wohi[(size_t)H_ * D_ * E_];
__device__ u16 g_wolo[(size_t)H_ * D_ * E_];
__device__ u16 g_chi[(size_t)B_ * T_ * H_ * D_];
__device__ u16 g_clo[(size_t)B_ * T_ * H_ * D_];

// ---------------- RoPE ----------------
__global__ __launch_bounds__(256) void rope_table_kernel() {
    int idx = blockIdx.x * 256 + threadIdx.x;
    int t = idx >> 6, d2 = idx & 63;
    double inv = pow(10000.0, -(double)(2 * d2) / 128.0);
    double ang = (double)t * inv;
    g_rope[idx] = make_float2((float)cos(ang), (float)sin(ang));
}

__global__ __launch_bounds__(256) void rope_apply_kernel(float* __restrict__ x, int heads, int total4) {
    int p = blockIdx.x * 256 + threadIdx.x;
    if (p >= total4) return;
    int cd = p & 31;
    int t = (p / (32 * heads)) % T_;
    float4 v = ((const float4*)x)[p];
    float2 r0 = g_rope[t * 64 + cd * 2];
    float2 r1 = g_rope[t * 64 + cd * 2 + 1];
    float a = v.x * r0.x - v.y * r0.y;
    float b = v.x * r0.y + v.y * r0.x;
    float c = v.z * r1.x - v.w * r1.y;
    float d = v.z * r1.y + v.w * r1.x;
    ((float4*)x)[p] = make_float4(a, b, c, d);
}

__device__ __forceinline__ float bf16_rnd(float x) {
    u32 u = __float_as_uint(x);
    u32 r = (u + 0x7fffu + ((u >> 16) & 1u)) & 0xffff0000u;
    return __uint_as_float(r);
}

// ---------------- split fp32 -> bf16 hi + lo ----------------
__global__ __launch_bounds__(256) void split_kernel(
    const float* __restrict__ x, u16* __restrict__ hi, u16* __restrict__ lo, int n2)
{
    int i = blockIdx.x * 256 + threadIdx.x;
    if (i >= n2) return;
    float2 v = ((const float2*)x)[i];
    float hx = bf16_rnd(v.x);
    float hy = bf16_rnd(v.y);
    float lx = bf16_rnd(v.x - hx);
    float ly = bf16_rnd(v.y - hy);
    u32 hw = (__float_as_uint(hx) >> 16) | (__float_as_uint(hy) & 0xffff0000u);
    u32 lw = (__float_as_uint(lx) >> 16) | (__float_as_uint(ly) & 0xffff0000u);
    ((u32*)hi)[i] = hw;
    ((u32*)lo)[i] = lw;
}

// ---------------- bf16x3 GEMM: 128x128 CTA tile, 512 threads, term-major ----------------
// C = Ahi*Bhi + Ahi*Blo + Alo*Bhi. A row-major [M][K], B row-major [K][N].
// 16 warps = 4m x 4n, warp tile 32x32. k-chunk 32, double-buffered.
// Smem uint4 units: A stage: 128 rows x 8 chunks (hi c0-3, lo c4-7), phys c^(r&7).
//                   B stage: 32 k-rows x 32 chunks (hi c0-15, lo c16-31), phys (within half) c^(k&7).
// Stages: A0 @0, A1 @1024, B0 @2048, B1 @3072.
#define GEMM_SMEM_BYTES 65536

__global__ __launch_bounds__(512) void hgemm3_kernel(
    const u16* __restrict__ Ahi, const u16* __restrict__ Alo,
    const u16* __restrict__ Bhi, const u16* __restrict__ Blo,
    float* __restrict__ C, int M, int N, int K)
{
    extern __shared__ uint4 sg[];
    const int tid = threadIdx.x;
    const int lane = tid & 31, w = tid >> 5;
    const int wm = w >> 2, wn = w & 3;
    const int bx = blockIdx.x, by = blockIdx.y;

    // global-load mapping
    const int arow = tid >> 2, ac4 = tid & 3;     // A: 1 uint4 hi + 1 lo per thread
    const int bkr = tid >> 4, bseg = tid & 15;    // B: 1 uint4 hi + 1 lo per thread

    const u16* pAh = Ahi + (size_t)(by * 128 + arow) * K + ac4 * 8;
    const u16* pAl = Alo + (size_t)(by * 128 + arow) * K + ac4 * 8;
    const u16* pBh = Bhi + (size_t)bkr * N + bx * 128 + bseg * 8;
    const u16* pBl = Blo + (size_t)bkr * N + bx * 128 + bseg * 8;

    const int sAh = arow * 8 + (ac4 ^ (arow & 7));
    const int sAl = arow * 8 + ((4 + ac4) ^ (arow & 7));
    const int sBh = bkr * 32 + (bseg ^ (bkr & 7));
    const int sBl = bkr * 32 + 16 + (bseg ^ (bkr & 7));

    // ldmatrix lane components
    const int kbit = (lane >> 4) & 1;
    const int aRowL = wm * 32 + (lane & 15);
    const int bkrS = (lane & 7) + ((lane >> 3) & 1) * 8;

    float acc[2][4][4];
#pragma unroll
    for (int mt = 0; mt < 2; mt++)
#pragma unroll
        for (int nt = 0; nt < 4; nt++)
#pragma unroll
            for (int e = 0; e < 4; e++) acc[mt][nt][e] = 0.0f;

    uint4 rah, ral, rbh, rbl;
    rah = *(const uint4*)pAh;
    ral = *(const uint4*)pAl;
    rbh = *(const uint4*)pBh;
    rbl = *(const uint4*)pBl;
    sg[sAh] = rah; sg[sAl] = ral;
    sg[2048 + sBh] = rbh; sg[2048 + sBl] = rbl;
    __syncthreads();

    const int nch = K >> 5;
    for (int kc = 1; kc <= nch; ++kc) {
        if (kc < nch) {
            rah = *(const uint4*)(pAh + kc * 32);
            ral = *(const uint4*)(pAl + kc * 32);
            rbh = *(const uint4*)(pBh + (size_t)kc * 32 * N);
            rbl = *(const uint4*)(pBl + (size_t)kc * 32 * N);
        }
        {
            const int st = (kc - 1) & 1;
            const uint4* smA = sg + st * 1024;
            const uint4* smB = sg + 2048 + st * 1024;
#pragma unroll
            for (int s = 0; s < 2; ++s) {
                u32 afr[2][2][4];   // [sp][mt]
#pragma unroll
                for (int sp = 0; sp < 2; ++sp)
#pragma unroll
                    for (int mt = 0; mt < 2; ++mt) {
                        int rr = aRowL + 16 * mt;
                        int idx = rr * 8 + ((2 * s + kbit + 4 * sp) ^ (rr & 7));
                        ldsm4(afr[sp][mt], sm_u32(smA + idx));
                    }
                u32 bfr[2][2][4];   // [sp][cc]
#pragma unroll
                for (int sp = 0; sp < 2; ++sp)
#pragma unroll
                    for (int cc = 0; cc < 2; ++cc) {
                        int cv = (wn * 4 + 2 * cc + kbit) ^ (bkrS & 7);
                        int idx = (bkrS + 16 * s) * 32 + sp * 16 + cv;
                        ldsm4t(bfr[sp][cc], sm_u32(smB + idx));
                    }
                // term-major: hh, hl, lh (acc separation = 8)
#pragma unroll
                for (int mt = 0; mt < 2; ++mt)
#pragma unroll
                    for (int cc = 0; cc < 2; ++cc) {
                        mma_bf16(acc[mt][2 * cc],     afr[0][mt], bfr[0][cc][0], bfr[0][cc][1]);
                        mma_bf16(acc[mt][2 * cc + 1], afr[0][mt], bfr[0][cc][2], bfr[0][cc][3]);
                    }
#pragma unroll
                for (int mt = 0; mt < 2; ++mt)
#pragma unroll
                    for (int cc = 0; cc < 2; ++cc) {
                        mma_bf16(acc[mt][2 * cc],     afr[0][mt], bfr[1][cc][0], bfr[1][cc][1]);
                        mma_bf16(acc[mt][2 * cc + 1], afr[0][mt], bfr[1][cc][2], bfr[1][cc][3]);
                    }
#pragma unroll
                for (int mt = 0; mt < 2; ++mt)
#pragma unroll
                    for (int cc = 0; cc < 2; ++cc) {
                        mma_bf16(acc[mt][2 * cc],     afr[1][mt], bfr[0][cc][0], bfr[0][cc][1]);
                        mma_bf16(acc[mt][2 * cc + 1], afr[1][mt], bfr[0][cc][2], bfr[0][cc][3]);
                    }
            }
        }
        if (kc < nch) {
            const int st = kc & 1;
            sg[st * 1024 + sAh] = rah;
            sg[st * 1024 + sAl] = ral;
            sg[2048 + st * 1024 + sBh] = rbh;
            sg[2048 + st * 1024 + sBl] = rbl;
            __syncthreads();
        }
    }

#pragma unroll
    for (int mt = 0; mt < 2; ++mt)
#pragma unroll
        for (int nt = 0; nt < 4; ++nt) {
            int gr = by * 128 + wm * 32 + mt * 16 + (lane >> 2);
            int gc = bx * 128 + wn * 32 + nt * 8 + (lane & 3) * 2;
            *(float2*)&C[(size_t)gr * N + gc] = make_float2(acc[mt][nt][0], acc[mt][nt][1]);
            *(float2*)&C[(size_t)(gr + 8) * N + gc] = make_float2(acc[mt][nt][2], acc[mt][nt][3]);
        }
}

// ---------------- Flash attention on mma.sync (bf16x3, term-major gg-pairs) ----------------
#define FSM_BYTES 196608

__device__ __forceinline__ u32 tile_addr(u32 base, int row, int chunk) {
    return base + (u32)(((row << 4) + (chunk ^ (row & 7))) << 4);
}

__global__ __launch_bounds__(256) void flashmma_kernel(
    const float* __restrict__ q, const float* __restrict__ k,
    const float* __restrict__ v, float* __restrict__ ctx)
{
    extern __shared__ char fsm[];
    uint4* Q4hi = (uint4*)fsm;
    uint4* Q4lo = (uint4*)(fsm + 32768);
    uint4* K4hi = (uint4*)(fsm + 65536);
    uint4* K4lo = (uint4*)(fsm + 98304);
    uint4* V4hi = (uint4*)(fsm + 131072);
    uint4* V4lo = (uint4*)(fsm + 163840);
    const u32 uQhi = sm_u32(Q4hi), uQlo = sm_u32(Q4lo);
    const u32 uKhi = sm_u32(K4hi), uKlo = sm_u32(K4lo);
    const u32 uVhi = sm_u32(V4hi), uVlo = sm_u32(V4lo);

    const int qt_ = (int)gridDim.x - 1 - (int)blockIdx.x;
    const int bh = blockIdx.y;
    const int b = bh >> 4;
    const int h = bh & 15;
    const int g = h >> 1;
    const int tid = threadIdx.x;
    const int lane = tid & 31, wid = tid >> 5;
    const int m0 = wid * 16;

    const size_t qbase = (((size_t)b * T_ + (size_t)qt_ * 128) * H_ + h) * D_;
#pragma unroll
    for (int it = 0; it < 8; ++it) {
        int f = it * 256 + tid;
        int r = f >> 4, c = f & 15;
        const float* src = q + qbase + (size_t)r * (H_ * D_) + c * 8;
        float4 a = *(const float4*)src;
        float4 bb = *(const float4*)(src + 4);
        float vals[8] = {a.x, a.y, a.z, a.w, bb.x, bb.y, bb.z, bb.w};
        u32 hw[4], lw[4];
#pragma unroll
        for (int j = 0; j < 4; ++j) {
            float v0 = vals[2 * j] * SCALE_, v1 = vals[2 * j + 1] * SCALE_;
            float h0 = bf16_rnd(v0), h1 = bf16_rnd(v1);
            float l0 = bf16_rnd(v0 - h0), l1 = bf16_rnd(v1 - h1);
            hw[j] = (__float_as_uint(h0) >> 16) | (__float_as_uint(h1) & 0xffff0000u);
            lw[j] = (__float_as_uint(l0) >> 16) | (__float_as_uint(l1) & 0xffff0000u);
        }
        int idx = r * 16 + (c ^ (r & 7));
        Q4hi[idx] = make_uint4(hw[0], hw[1], hw[2], hw[3]);
        Q4lo[idx] = make_uint4(lw[0], lw[1], lw[2], lw[3]);
    }

    float oc[16][4];
#pragma unroll
    for (int t = 0; t < 16; ++t)
#pragma unroll
        for (int e = 0; e < 4; ++e) oc[t][e] = 0.0f;
    float mA = -1e30f, mB = -1e30f, lA = 0.0f, lB = 0.0f;

    __syncthreads();

    for (int kt = 0; kt <= qt_; ++kt) {
        const size_t kvbase = (((size_t)b * T_ + (size_t)kt * 128) * KVH_ + g) * D_;
#pragma unroll
        for (int it = 0; it < 8; ++it) {
            int f = it * 256 + tid;
            int r = f >> 4, c = f & 15;
            const float* ks = k + kvbase + (size_t)r * (KVH_ * D_) + c * 8;
            const float* vs = v + kvbase + (size_t)r * (KVH_ * D_) + c * 8;
            float4 ka = *(const float4*)ks;
            float4 kb = *(const float4*)(ks + 4);
            float4 va = *(const float4*)vs;
            float4 vb = *(const float4*)(vs + 4);
            float kv8[8] = {ka.x, ka.y, ka.z, ka.w, kb.x, kb.y, kb.z, kb.w};
            float vv8[8] = {va.x, va.y, va.z, va.w, vb.x, vb.y, vb.z, vb.w};
            u32 khw[4], klw[4], vhw[4], vlw[4];
#pragma unroll
            for (int j = 0; j < 4; ++j) {
                float k0 = kv8[2 * j], k1 = kv8[2 * j + 1];
                float kh0 = bf16_rnd(k0), kh1 = bf16_rnd(k1);
                float kl0 = bf16_rnd(k0 - kh0), kl1 = bf16_rnd(k1 - kh1);
                khw[j] = (__float_as_uint(kh0) >> 16) | (__float_as_uint(kh1) & 0xffff0000u);
                klw[j] = (__float_as_uint(kl0) >> 16) | (__float_as_uint(kl1) & 0xffff0000u);
                float w0 = vv8[2 * j], w1 = vv8[2 * j + 1];
                float vh0 = bf16_rnd(w0), vh1 = bf16_rnd(w1);
                float vl0 = bf16_rnd(w0 - vh0), vl1 = bf16_rnd(w1 - vh1);
                vhw[j] = (__float_as_uint(vh0) >> 16) | (__float_as_uint(vh1) & 0xffff0000u);
                vlw[j] = (__float_as_uint(vl0) >> 16) | (__float_as_uint(vl1) & 0xffff0000u);
            }
            int idx = r * 16 + (c ^ (r & 7));
            K4hi[idx] = make_uint4(khw[0], khw[1], khw[2], khw[3]);
            K4lo[idx] = make_uint4(klw[0], klw[1], klw[2], klw[3]);
            V4hi[idx] = make_uint4(vhw[0], vhw[1], vhw[2], vhw[3]);
            V4lo[idx] = make_uint4(vlw[0], vlw[1], vlw[2], vlw[3]);
        }
        __syncthreads();

        // ---- phase A: S = Q K^T (bf16x3, gg-pairs, term-major) ----
        float sc[16][4];
#pragma unroll
        for (int t = 0; t < 16; ++t)
#pragma unroll
            for (int e = 0; e < 4; ++e) sc[t][e] = 0.0f;

#pragma unroll
        for (int kt16 = 0; kt16 < 8; ++kt16) {
            const int arow = m0 + (lane & 15);
            const int ac = 2 * kt16 + (lane >> 4);
            u32 ah[4], al[4];
            ldsm4(ah, tile_addr(uQhi, arow, ac));
            ldsm4(al, tile_addr(uQlo, arow, ac));
#pragma unroll
            for (int gp = 0; gp < 4; ++gp) {
                const int brow0 = (2 * gp) * 16 + (lane & 15);
                const int brow1 = (2 * gp + 1) * 16 + (lane & 15);
                u32 kh0[4], kl0[4], kh1[4], kl1[4];
                ldsm4(kh0, tile_addr(uKhi, brow0, ac));
                ldsm4(kl0, tile_addr(uKlo, brow0, ac));
                ldsm4(kh1, tile_addr(uKhi, brow1, ac));
                ldsm4(kl1, tile_addr(uKlo, brow1, ac));
                float* c00 = sc[4 * gp];
                float* c01 = sc[4 * gp + 1];
                float* c10 = sc[4 * gp + 2];
                float* c11 = sc[4 * gp + 3];
                mma_bf16(c00, ah, kh0[0], kh0[2]);
                mma_bf16(c01, ah, kh0[1], kh0[3]);
                mma_bf16(c10, ah, kh1[0], kh1[2]);
                mma_bf16(c11, ah, kh1[1], kh1[3]);
                mma_bf16(c00, ah, kl0[0], kl0[2]);
                mma_bf16(c01, ah, kl0[1], kl0[3]);
                mma_bf16(c10, ah, kl1[0], kl1[2]);
                mma_bf16(c11, ah, kl1[1], kl1[3]);
                mma_bf16(c00, al, kh0[0], kh0[2]);
                mma_bf16(c01, al, kh0[1], kh0[3]);
                mma_bf16(c10, al, kh1[0], kh1[2]);
                mma_bf16(c11, al, kh1[1], kh1[3]);
            }
        }

        if (kt == qt_) {
            int rl = m0 + (lane >> 2);
#pragma unroll
            for (int t = 0; t < 16; ++t) {
                int c0 = t * 8 + 2 * (lane & 3);
                if (c0 > rl)     sc[t][0] = -1e30f;
                if (c0 + 1 > rl) sc[t][1] = -1e30f;
                if (c0 > rl + 8)     sc[t][2] = -1e30f;
                if (c0 + 1 > rl + 8) sc[t][3] = -1e30f;
            }
        }

        {
            float mxA = -1e30f, mxB = -1e30f;
#pragma unroll
            for (int t = 0; t < 16; ++t) {
                mxA = fmaxf(mxA, fmaxf(sc[t][0], sc[t][1]));
                mxB = fmaxf(mxB, fmaxf(sc[t][2], sc[t][3]));
            }
            mxA = fmaxf(mxA, __shfl_xor_sync(0xffffffffu, mxA, 1));
            mxA = fmaxf(mxA, __shfl_xor_sync(0xffffffffu, mxA, 2));
            mxB = fmaxf(mxB, __shfl_xor_sync(0xffffffffu, mxB, 1));
            mxB = fmaxf(mxB, __shfl_xor_sync(0xffffffffu, mxB, 2));
            float mnA = fmaxf(mA, mxA), mnB = fmaxf(mB, mxB);
            float sA = 0.0f, sB = 0.0f;
#pragma unroll
            for (int t = 0; t < 16; ++t) {
                sc[t][0] = __expf(sc[t][0] - mnA);
                sc[t][1] = __expf(sc[t][1] - mnA);
                sc[t][2] = __expf(sc[t][2] - mnB);
                sc[t][3] = __expf(sc[t][3] - mnB);
                sA += sc[t][0] + sc[t][1];
                sB += sc[t][2] + sc[t][3];
            }
            sA += __shfl_xor_sync(0xffffffffu, sA, 1);
            sA += __shfl_xor_sync(0xffffffffu, sA, 2);
            sB += __shfl_xor_sync(0xffffffffu, sB, 1);
            sB += __shfl_xor_sync(0xffffffffu, sB, 2);
            float alA = __expf(mA - mnA), alB = __expf(mB - mnB);
            lA = lA * alA + sA;  mA = mnA;
            lB = lB * alB + sB;  mB = mnB;
#pragma unroll
            for (int t = 0; t < 16; ++t) {
                oc[t][0] *= alA; oc[t][1] *= alA;
                oc[t][2] *= alB; oc[t][3] *= alB;
            }
        }

        // ---- phase B: O += P V (bf16x3, gg-pairs, term-major) ----
#pragma unroll
        for (int kt2 = 0; kt2 < 8; ++kt2) {
            u32 pah[4], pal[4];
#pragma unroll
            for (int j = 0; j < 4; ++j) {
                int t = 2 * kt2 + (j >> 1);
                int e = (j & 1) * 2;
                float p0 = sc[t][e], p1 = sc[t][e + 1];
                u32 hp = mk_bf2(p0, p1);
                float r0 = p0 - __uint_as_float(hp << 16);
                float r1 = p1 - __uint_as_float(hp & 0xffff0000u);
                pah[j] = hp;
                pal[j] = mk_bf2(r0, r1);
            }
            const int vrow = kt2 * 16 + (lane & 15);
#pragma unroll
            for (int gp = 0; gp < 4; ++gp) {
                const int vc0 = 2 * (2 * gp) + (lane >> 4);
                const int vc1 = 2 * (2 * gp + 1) + (lane >> 4);
                u32 vh0[4], vl0[4], vh1[4], vl1[4];
                ldsm4t(vh0, tile_addr(uVhi, vrow, vc0));
                ldsm4t(vl0, tile_addr(uVlo, vrow, vc0));
                ldsm4t(vh1, tile_addr(uVhi, vrow, vc1));
                ldsm4t(vl1, tile_addr(uVlo, vrow, vc1));
                float* o00 = oc[4 * gp];
                float* o01 = oc[4 * gp + 1];
                float* o10 = oc[4 * gp + 2];
                float* o11 = oc[4 * gp + 3];
                mma_bf16(o00, pah, vh0[0], vh0[1]);
                mma_bf16(o01, pah, vh0[2], vh0[3]);
                mma_bf16(o10, pah, vh1[0], vh1[1]);
                mma_bf16(o11, pah, vh1[2], vh1[3]);
                mma_bf16(o00, pah, vl0[0], vl0[1]);
                mma_bf16(o01, pah, vl0[2], vl0[3]);
                mma_bf16(o10, pah, vl1[0], vl1[1]);
                mma_bf16(o11, pah, vl1[2], vl1[3]);
                mma_bf16(o00, pal, vh0[0], vh0[1]);
                mma_bf16(o01, pal, vh0[2], vh0[3]);
                mma_bf16(o10, pal, vh1[0], vh1[1]);
                mma_bf16(o11, pal, vh1[2], vh1[3]);
            }
        }
        __syncthreads();
    }

    {
        float iA = 1.0f / lA, iB = 1.0f / lB;
        int rA = qt_ * 128 + m0 + (lane >> 2);
        int rB = rA + 8;
        size_t baseA = (((size_t)b * T_ + rA) * H_ + h) * D_;
        size_t baseB = (((size_t)b * T_ + rB) * H_ + h) * D_;
        int cb = 2 * (lane & 3);
#pragma unroll
        for (int t = 0; t < 16; ++t) {
            int col = t * 8 + cb;
            *(float2*)&ctx[baseA + col] = make_float2(oc[t][0] * iA, oc[t][1] * iA);
            *(float2*)&ctx[baseB + col] = make_float2(oc[t][2] * iB, oc[t][3] * iB);
        }
    }
}

// ---------------- launch ----------------
extern "C" void kernel_launch(void* const* d_in, const int* in_sizes, int n_in,
                              void* d_out, int out_size)
{
    const float* x  = (const float*)d_in[0];
    const float* wq = (const float*)d_in[2];
    const float* wk = (const float*)d_in[3];
    const float* wv = (const float*)d_in[4];
    const float* wo = (const float*)d_in[5];
    float* out = (float*)d_out;

    float *gq, *gk, *gv, *gctx;
    u16 *xhi, *xlo, *wqhi, *wqlo, *wkhi, *wklo, *wvhi, *wvlo, *wohi, *wolo, *chi, *clo;
    cudaGetSymbolAddress((void**)&gq,   g_q);
    cudaGetSymbolAddress((void**)&gk,   g_k);
    cudaGetSymbolAddress((void**)&gv,   g_v);
    cudaGetSymbolAddress((void**)&gctx, g_ctx);
    cudaGetSymbolAddress((void**)&xhi,  g_xhi);
    cudaGetSymbolAddress((void**)&xlo,  g_xlo);
    cudaGetSymbolAddress((void**)&wqhi, g_wqhi);
    cudaGetSymbolAddress((void**)&wqlo, g_wqlo);
    cudaGetSymbolAddress((void**)&wkhi, g_wkhi);
    cudaGetSymbolAddress((void**)&wklo, g_wklo);
    cudaGetSymbolAddress((void**)&wvhi, g_wvhi);
    cudaGetSymbolAddress((void**)&wvlo, g_wvlo);
    cudaGetSymbolAddress((void**)&wohi, g_wohi);
    cudaGetSymbolAddress((void**)&wolo, g_wolo);
    cudaGetSymbolAddress((void**)&chi,  g_chi);
    cudaGetSymbolAddress((void**)&clo,  g_clo);

    const int M = B_ * T_;
    const int HD = H_ * D_;
    const int KD = KVH_ * D_;

    cudaFuncSetAttribute(hgemm3_kernel, cudaFuncAttributeMaxDynamicSharedMemorySize, GEMM_SMEM_BYTES);
    cudaFuncSetAttribute(flashmma_kernel, cudaFuncAttributeMaxDynamicSharedMemorySize, FSM_BYTES);

    rope_table_kernel<<<(T_ * 64) / 256, 256>>>();

    split_kernel<<<(M * E_ / 2) / 256, 256>>>(x, xhi, xlo, M * E_ / 2);
    split_kernel<<<(E_ * HD / 2) / 256, 256>>>(wq, wqhi, wqlo, E_ * HD / 2);
    split_kernel<<<(E_ * KD / 2) / 256, 256>>>(wk, wkhi, wklo, E_ * KD / 2);
    split_kernel<<<(E_ * KD / 2) / 256, 256>>>(wv, wvhi, wvlo, E_ * KD / 2);
    split_kernel<<<(HD * E_ / 2) / 256, 256>>>(wo, wohi, wolo, HD * E_ / 2);

    hgemm3_kernel<<<dim3(HD / 128, M / 128), 512, GEMM_SMEM_BYTES>>>(xhi, xlo, wqhi, wqlo, gq, M, HD, E_);
    hgemm3_kernel<<<dim3(KD / 128, M / 128), 512, GEMM_SMEM_BYTES>>>(xhi, xlo, wkhi, wklo, gk, M, KD, E_);
    hgemm3_kernel<<<dim3(KD / 128, M / 128), 512, GEMM_SMEM_BYTES>>>(xhi, xlo, wvhi, wvlo, gv, M, KD, E_);

    int nq4 = B_ * T_ * H_ * (D_ / 4);
    int nk4 = B_ * T_ * KVH_ * (D_ / 4);
    rope_apply_kernel<<<nq4 / 256, 256>>>(gq, H_, nq4);
    rope_apply_kernel<<<nk4 / 256, 256>>>(gk, KVH_, nk4);

    flashmma_kernel<<<dim3(T_ / 128, B_ * H_), 256, FSM_BYTES>>>(gq, gk, gv, gctx);

    split_kernel<<<(M * HD / 2) / 256, 256>>>(gctx, chi, clo, M * HD / 2);
    hgemm3_kernel<<<dim3(E_ / 128, M / 128), 512, GEMM_SMEM_BYTES>>>(chi, clo, wohi, wolo, out, M, E_, HD);
}

// round 16
// speedup vs baseline: 2.5706x; 1.0361x over previous
#include <cuda_runtime.h>
#include <cuda_bf16.h>
#include <math.h>

#define B_ 2
#define T_ 2048
#define E_ 2048
#define H_ 16
#define KVH_ 8
#define D_ 128
#define SCALE_ 0.08838834764831845f

typedef unsigned long long ull;
typedef unsigned int u32;
typedef unsigned short u16;

// ---------------- mma / ldmatrix wrappers ----------------
__device__ __forceinline__ u32 sm_u32(const void* p) {
    return (u32)__cvta_generic_to_shared(p);
}
__device__ __forceinline__ void ldsm4(u32* r, u32 addr) {
    asm volatile("ldmatrix.sync.aligned.m8n8.x4.shared.b16 {%0,%1,%2,%3}, [%4];"
                 : "=r"(r[0]), "=r"(r[1]), "=r"(r[2]), "=r"(r[3]) : "r"(addr));
}
__device__ __forceinline__ void ldsm4t(u32* r, u32 addr) {
    asm volatile("ldmatrix.sync.aligned.m8n8.x4.trans.shared.b16 {%0,%1,%2,%3}, [%4];"
                 : "=r"(r[0]), "=r"(r[1]), "=r"(r[2]), "=r"(r[3]) : "r"(addr));
}
__device__ __forceinline__ void mma_bf16(float* c, const u32* a, u32 b0, u32 b1) {
    asm volatile("mma.sync.aligned.m16n8k16.row.col.f32.bf16.bf16.f32 "
                 "{%0,%1,%2,%3}, {%4,%5,%6,%7}, {%8,%9}, {%0,%1,%2,%3};"
                 : "+f"(c[0]), "+f"(c[1]), "+f"(c[2]), "+f"(c[3])
                 : "r"(a[0]), "r"(a[1]), "r"(a[2]), "r"(a[3]), "r"(b0), "r"(b1));
}
__device__ __forceinline__ u32 mk_bf2(float lo, float hi) {
    u32 r;
    asm("cvt.rn.bf16x2.f32 %0, %1, %2;" : "=r"(r) : "f"(hi), "f"(lo));
    return r;
}

__device__ __forceinline__ float bf16_rnd(float x) {
    u32 u = __float_as_uint(x);
    u32 r = (u + 0x7fffu + ((u >> 16) & 1u)) & 0xffff0000u;
    return __uint_as_float(r);
}
// split a float pair into packed bf16 hi-word and lo-word
__device__ __forceinline__ void split_pair(float v0, float v1, u32& hw, u32& lw) {
    float h0 = bf16_rnd(v0), h1 = bf16_rnd(v1);
    float l0 = bf16_rnd(v0 - h0), l1 = bf16_rnd(v1 - h1);
    hw = (__float_as_uint(h0) >> 16) | (__float_as_uint(h1) & 0xffff0000u);
    lw = (__float_as_uint(l0) >> 16) | (__float_as_uint(l1) & 0xffff0000u);
}

// ---------------- scratch ----------------
__device__ float2 g_rope[T_ * 64];

__device__ u16 g_xhi[(size_t)B_ * T_ * E_];
__device__ u16 g_xlo[(size_t)B_ * T_ * E_];
__device__ u16 g_wqhi[(size_t)E_ * H_ * D_];
__device__ u16 g_wqlo[(size_t)E_ * H_ * D_];
__device__ u16 g_wkhi[(size_t)E_ * KVH_ * D_];
__device__ u16 g_wklo[(size_t)E_ * KVH_ * D_];
__device__ u16 g_wvhi[(size_t)E_ * KVH_ * D_];
__device__ u16 g_wvlo[(size_t)E_ * KVH_ * D_];
__device__ u16 g_wohi[(size_t)H_ * D_ * E_];
__device__ u16 g_wolo[(size_t)H_ * D_ * E_];

__device__ u16 g_qhi[(size_t)B_ * T_ * H_ * D_];
__device__ u16 g_qlo[(size_t)B_ * T_ * H_ * D_];
__device__ u16 g_khi[(size_t)B_ * T_ * KVH_ * D_];
__device__ u16 g_klo[(size_t)B_ * T_ * KVH_ * D_];
__device__ u16 g_vhi[(size_t)B_ * T_ * KVH_ * D_];
__device__ u16 g_vlo[(size_t)B_ * T_ * KVH_ * D_];
__device__ u16 g_chi[(size_t)B_ * T_ * H_ * D_];
__device__ u16 g_clo[(size_t)B_ * T_ * H_ * D_];

// ---------------- RoPE table ----------------
__global__ __launch_bounds__(256) void rope_table_kernel() {
    int idx = blockIdx.x * 256 + threadIdx.x;
    int t = idx >> 6, d2 = idx & 63;
    double inv = pow(10000.0, -(double)(2 * d2) / 128.0);
    double ang = (double)t * inv;
    g_rope[idx] = make_float2((float)cos(ang), (float)sin(ang));
}

// ---------------- split fp32 -> bf16 hi + lo ----------------
__global__ __launch_bounds__(256) void split_kernel(
    const float* __restrict__ x, u16* __restrict__ hi, u16* __restrict__ lo, int n2)
{
    int i = blockIdx.x * 256 + threadIdx.x;
    if (i >= n2) return;
    float2 v = ((const float2*)x)[i];
    u32 hw, lw;
    split_pair(v.x, v.y, hw, lw);
    ((u32*)hi)[i] = hw;
    ((u32*)lo)[i] = lw;
}

// ---------------- bf16x3 GEMM, 128x128 CTA, 512 thr, fused epilogues ----------------
// mode 0: C fp32 out.  mode 1: rope+scale+split (q).  mode 2: rope+split (k).
// mode 3: split only (v).
#define GEMM_SMEM_BYTES 65536

__global__ __launch_bounds__(512) void hgemm3_kernel(
    const u16* __restrict__ Ahi, const u16* __restrict__ Alo,
    const u16* __restrict__ Bhi, const u16* __restrict__ Blo,
    float* __restrict__ Cf, u16* __restrict__ Chi, u16* __restrict__ Clo,
    int M, int N, int K, int mode)
{
    extern __shared__ uint4 sg[];
    const int tid = threadIdx.x;
    const int lane = tid & 31, w = tid >> 5;
    const int wm = w >> 2, wn = w & 3;
    const int bx = blockIdx.x, by = blockIdx.y;

    const int arow = tid >> 2, ac4 = tid & 3;
    const int bkr = tid >> 4, bseg = tid & 15;

    const u16* pAh = Ahi + (size_t)(by * 128 + arow) * K + ac4 * 8;
    const u16* pAl = Alo + (size_t)(by * 128 + arow) * K + ac4 * 8;
    const u16* pBh = Bhi + (size_t)bkr * N + bx * 128 + bseg * 8;
    const u16* pBl = Blo + (size_t)bkr * N + bx * 128 + bseg * 8;

    const int sAh = arow * 8 + (ac4 ^ (arow & 7));
    const int sAl = arow * 8 + ((4 + ac4) ^ (arow & 7));
    const int sBh = bkr * 32 + (bseg ^ (bkr & 7));
    const int sBl = bkr * 32 + 16 + (bseg ^ (bkr & 7));

    const int kbit = (lane >> 4) & 1;
    const int aRowL = wm * 32 + (lane & 15);
    const int bkrS = (lane & 7) + ((lane >> 3) & 1) * 8;

    float acc[2][4][4];
#pragma unroll
    for (int mt = 0; mt < 2; mt++)
#pragma unroll
        for (int nt = 0; nt < 4; nt++)
#pragma unroll
            for (int e = 0; e < 4; e++) acc[mt][nt][e] = 0.0f;

    uint4 rah, ral, rbh, rbl;
    rah = *(const uint4*)pAh;
    ral = *(const uint4*)pAl;
    rbh = *(const uint4*)pBh;
    rbl = *(const uint4*)pBl;
    sg[sAh] = rah; sg[sAl] = ral;
    sg[2048 + sBh] = rbh; sg[2048 + sBl] = rbl;
    __syncthreads();

    const int nch = K >> 5;
    for (int kc = 1; kc <= nch; ++kc) {
        if (kc < nch) {
            rah = *(const uint4*)(pAh + kc * 32);
            ral = *(const uint4*)(pAl + kc * 32);
            rbh = *(const uint4*)(pBh + (size_t)kc * 32 * N);
            rbl = *(const uint4*)(pBl + (size_t)kc * 32 * N);
        }
        {
            const int st = (kc - 1) & 1;
            const uint4* smA = sg + st * 1024;
            const uint4* smB = sg + 2048 + st * 1024;
#pragma unroll
            for (int s = 0; s < 2; ++s) {
                u32 afr[2][2][4];
#pragma unroll
                for (int sp = 0; sp < 2; ++sp)
#pragma unroll
                    for (int mt = 0; mt < 2; ++mt) {
                        int rr = aRowL + 16 * mt;
                        int idx = rr * 8 + ((2 * s + kbit + 4 * sp) ^ (rr & 7));
                        ldsm4(afr[sp][mt], sm_u32(smA + idx));
                    }
                u32 bfr[2][2][4];
#pragma unroll
                for (int sp = 0; sp < 2; ++sp)
#pragma unroll
                    for (int cc = 0; cc < 2; ++cc) {
                        int cv = (wn * 4 + 2 * cc + kbit) ^ (bkrS & 7);
                        int idx = (bkrS + 16 * s) * 32 + sp * 16 + cv;
                        ldsm4t(bfr[sp][cc], sm_u32(smB + idx));
                    }
#pragma unroll
                for (int mt = 0; mt < 2; ++mt)
#pragma unroll
                    for (int cc = 0; cc < 2; ++cc) {
                        mma_bf16(acc[mt][2 * cc],     afr[0][mt], bfr[0][cc][0], bfr[0][cc][1]);
                        mma_bf16(acc[mt][2 * cc + 1], afr[0][mt], bfr[0][cc][2], bfr[0][cc][3]);
                    }
#pragma unroll
                for (int mt = 0; mt < 2; ++mt)
#pragma unroll
                    for (int cc = 0; cc < 2; ++cc) {
                        mma_bf16(acc[mt][2 * cc],     afr[0][mt], bfr[1][cc][0], bfr[1][cc][1]);
                        mma_bf16(acc[mt][2 * cc + 1], afr[0][mt], bfr[1][cc][2], bfr[1][cc][3]);
                    }
#pragma unroll
                for (int mt = 0; mt < 2; ++mt)
#pragma unroll
                    for (int cc = 0; cc < 2; ++cc) {
                        mma_bf16(acc[mt][2 * cc],     afr[1][mt], bfr[0][cc][0], bfr[0][cc][1]);
                        mma_bf16(acc[mt][2 * cc + 1], afr[1][mt], bfr[0][cc][2], bfr[0][cc][3]);
                    }
            }
        }
        if (kc < nch) {
            const int st = kc & 1;
            sg[st * 1024 + sAh] = rah;
            sg[st * 1024 + sAl] = ral;
            sg[2048 + st * 1024 + sBh] = rbh;
            sg[2048 + st * 1024 + sBl] = rbl;
            __syncthreads();
        }
    }

    // ---- epilogue ----
#pragma unroll
    for (int mt = 0; mt < 2; ++mt)
#pragma unroll
        for (int nt = 0; nt < 4; ++nt) {
            int gr = by * 128 + wm * 32 + mt * 16 + (lane >> 2);
            int gc = bx * 128 + wn * 32 + nt * 8 + (lane & 3) * 2;
            float e0 = acc[mt][nt][0], e1 = acc[mt][nt][1];
            float f0 = acc[mt][nt][2], f1 = acc[mt][nt][3];
            if (mode == 0) {
                *(float2*)&Cf[(size_t)gr * N + gc] = make_float2(e0, e1);
                *(float2*)&Cf[(size_t)(gr + 8) * N + gc] = make_float2(f0, f1);
            } else {
                if (mode <= 2) {
                    int t0 = gr & (T_ - 1);
                    int d2 = (gc & 127) >> 1;
                    float2 cs0 = g_rope[t0 * 64 + d2];
                    float2 cs1 = g_rope[(t0 + 8) * 64 + d2];
                    float a0 = e0 * cs0.x - e1 * cs0.y;
                    float a1 = e0 * cs0.y + e1 * cs0.x;
                    float b0 = f0 * cs1.x - f1 * cs1.y;
                    float b1 = f0 * cs1.y + f1 * cs1.x;
                    e0 = a0; e1 = a1; f0 = b0; f1 = b1;
                    if (mode == 1) {
                        e0 *= SCALE_; e1 *= SCALE_;
                        f0 *= SCALE_; f1 *= SCALE_;
                    }
                }
                u32 hw, lw;
                split_pair(e0, e1, hw, lw);
                size_t o0 = ((size_t)gr * N + gc) >> 1;
                ((u32*)Chi)[o0] = hw;
                ((u32*)Clo)[o0] = lw;
                split_pair(f0, f1, hw, lw);
                size_t o1 = ((size_t)(gr + 8) * N + gc) >> 1;
                ((u32*)Chi)[o1] = hw;
                ((u32*)Clo)[o1] = lw;
            }
        }
}

// ---------------- Flash attention on mma.sync (bf16x3, pre-split inputs) ----------------
#define FSM_BYTES 196608

__device__ __forceinline__ u32 tile_addr(u32 base, int row, int chunk) {
    return base + (u32)(((row << 4) + (chunk ^ (row & 7))) << 4);
}

__global__ __launch_bounds__(256) void flashmma_kernel(
    const u16* __restrict__ qhi, const u16* __restrict__ qlo,
    const u16* __restrict__ khi, const u16* __restrict__ klo,
    const u16* __restrict__ vhi, const u16* __restrict__ vlo,
    u16* __restrict__ chi, u16* __restrict__ clo)
{
    extern __shared__ char fsm[];
    uint4* Q4hi = (uint4*)fsm;
    uint4* Q4lo = (uint4*)(fsm + 32768);
    uint4* K4hi = (uint4*)(fsm + 65536);
    uint4* K4lo = (uint4*)(fsm + 98304);
    uint4* V4hi = (uint4*)(fsm + 131072);
    uint4* V4lo = (uint4*)(fsm + 163840);
    const u32 uQhi = sm_u32(Q4hi), uQlo = sm_u32(Q4lo);
    const u32 uKhi = sm_u32(K4hi), uKlo = sm_u32(K4lo);
    const u32 uVhi = sm_u32(V4hi), uVlo = sm_u32(V4lo);

    const int qt_ = (int)gridDim.x - 1 - (int)blockIdx.x;
    const int bh = blockIdx.y;
    const int b = bh >> 4;
    const int h = bh & 15;
    const int g = h >> 1;
    const int tid = threadIdx.x;
    const int lane = tid & 31, wid = tid >> 5;
    const int m0 = wid * 16;

    // ---- load pre-split Q tiles (plain copies) ----
    const size_t qbase = (((size_t)b * T_ + (size_t)qt_ * 128) * H_ + h) * D_;
#pragma unroll
    for (int it = 0; it < 8; ++it) {
        int f = it * 256 + tid;
        int r = f >> 4, c = f & 15;
        size_t off = qbase + (size_t)r * (H_ * D_) + c * 8;
        int idx = r * 16 + (c ^ (r & 7));
        Q4hi[idx] = *(const uint4*)(qhi + off);
        Q4lo[idx] = *(const uint4*)(qlo + off);
    }

    float oc[16][4];
#pragma unroll
    for (int t = 0; t < 16; ++t)
#pragma unroll
        for (int e = 0; e < 4; ++e) oc[t][e] = 0.0f;
    float mA = -1e30f, mB = -1e30f, lA = 0.0f, lB = 0.0f;

    __syncthreads();

    for (int kt = 0; kt <= qt_; ++kt) {
        const size_t kvbase = (((size_t)b * T_ + (size_t)kt * 128) * KVH_ + g) * D_;
#pragma unroll
        for (int it = 0; it < 8; ++it) {
            int f = it * 256 + tid;
            int r = f >> 4, c = f & 15;
            size_t off = kvbase + (size_t)r * (KVH_ * D_) + c * 8;
            int idx = r * 16 + (c ^ (r & 7));
            K4hi[idx] = *(const uint4*)(khi + off);
            K4lo[idx] = *(const uint4*)(klo + off);
            V4hi[idx] = *(const uint4*)(vhi + off);
            V4lo[idx] = *(const uint4*)(vlo + off);
        }
        __syncthreads();

        // ---- phase A: S = Q K^T ----
        float sc[16][4];
#pragma unroll
        for (int t = 0; t < 16; ++t)
#pragma unroll
            for (int e = 0; e < 4; ++e) sc[t][e] = 0.0f;

#pragma unroll
        for (int kt16 = 0; kt16 < 8; ++kt16) {
            const int arow = m0 + (lane & 15);
            const int ac = 2 * kt16 + (lane >> 4);
            u32 ah[4], al[4];
            ldsm4(ah, tile_addr(uQhi, arow, ac));
            ldsm4(al, tile_addr(uQlo, arow, ac));
#pragma unroll
            for (int gp = 0; gp < 4; ++gp) {
                const int brow0 = (2 * gp) * 16 + (lane & 15);
                const int brow1 = (2 * gp + 1) * 16 + (lane & 15);
                u32 kh0[4], kl0[4], kh1[4], kl1[4];
                ldsm4(kh0, tile_addr(uKhi, brow0, ac));
                ldsm4(kl0, tile_addr(uKlo, brow0, ac));
                ldsm4(kh1, tile_addr(uKhi, brow1, ac));
                ldsm4(kl1, tile_addr(uKlo, brow1, ac));
                float* c00 = sc[4 * gp];
                float* c01 = sc[4 * gp + 1];
                float* c10 = sc[4 * gp + 2];
                float* c11 = sc[4 * gp + 3];
                mma_bf16(c00, ah, kh0[0], kh0[2]);
                mma_bf16(c01, ah, kh0[1], kh0[3]);
                mma_bf16(c10, ah, kh1[0], kh1[2]);
                mma_bf16(c11, ah, kh1[1], kh1[3]);
                mma_bf16(c00, ah, kl0[0], kl0[2]);
                mma_bf16(c01, ah, kl0[1], kl0[3]);
                mma_bf16(c10, ah, kl1[0], kl1[2]);
                mma_bf16(c11, ah, kl1[1], kl1[3]);
                mma_bf16(c00, al, kh0[0], kh0[2]);
                mma_bf16(c01, al, kh0[1], kh0[3]);
                mma_bf16(c10, al, kh1[0], kh1[2]);
                mma_bf16(c11, al, kh1[1], kh1[3]);
            }
        }

        if (kt == qt_) {
            int rl = m0 + (lane >> 2);
#pragma unroll
            for (int t = 0; t < 16; ++t) {
                int c0 = t * 8 + 2 * (lane & 3);
                if (c0 > rl)     sc[t][0] = -1e30f;
                if (c0 + 1 > rl) sc[t][1] = -1e30f;
                if (c0 > rl + 8)     sc[t][2] = -1e30f;
                if (c0 + 1 > rl + 8) sc[t][3] = -1e30f;
            }
        }

        {
            float mxA = -1e30f, mxB = -1e30f;
#pragma unroll
            for (int t = 0; t < 16; ++t) {
                mxA = fmaxf(mxA, fmaxf(sc[t][0], sc[t][1]));
                mxB = fmaxf(mxB, fmaxf(sc[t][2], sc[t][3]));
            }
            mxA = fmaxf(mxA, __shfl_xor_sync(0xffffffffu, mxA, 1));
            mxA = fmaxf(mxA, __shfl_xor_sync(0xffffffffu, mxA, 2));
            mxB = fmaxf(mxB, __shfl_xor_sync(0xffffffffu, mxB, 1));
            mxB = fmaxf(mxB, __shfl_xor_sync(0xffffffffu, mxB, 2));
            float mnA = fmaxf(mA, mxA), mnB = fmaxf(mB, mxB);
            float sA = 0.0f, sB = 0.0f;
#pragma unroll
            for (int t = 0; t < 16; ++t) {
                sc[t][0] = __expf(sc[t][0] - mnA);
                sc[t][1] = __expf(sc[t][1] - mnA);
                sc[t][2] = __expf(sc[t][2] - mnB);
                sc[t][3] = __expf(sc[t][3] - mnB);
                sA += sc[t][0] + sc[t][1];
                sB += sc[t][2] + sc[t][3];
            }
            sA += __shfl_xor_sync(0xffffffffu, sA, 1);
            sA += __shfl_xor_sync(0xffffffffu, sA, 2);
            sB += __shfl_xor_sync(0xffffffffu, sB, 1);
            sB += __shfl_xor_sync(0xffffffffu, sB, 2);
            float alA = __expf(mA - mnA), alB = __expf(mB - mnB);
            lA = lA * alA + sA;  mA = mnA;
            lB = lB * alB + sB;  mB = mnB;
#pragma unroll
            for (int t = 0; t < 16; ++t) {
                oc[t][0] *= alA; oc[t][1] *= alA;
                oc[t][2] *= alB; oc[t][3] *= alB;
            }
        }

        // ---- phase B: O += P V ----
#pragma unroll
        for (int kt2 = 0; kt2 < 8; ++kt2) {
            u32 pah[4], pal[4];
#pragma unroll
            for (int j = 0; j < 4; ++j) {
                int t = 2 * kt2 + (j >> 1);
                int e = (j & 1) * 2;
                float p0 = sc[t][e], p1 = sc[t][e + 1];
                u32 hp = mk_bf2(p0, p1);
                float r0 = p0 - __uint_as_float(hp << 16);
                float r1 = p1 - __uint_as_float(hp & 0xffff0000u);
                pah[j] = hp;
                pal[j] = mk_bf2(r0, r1);
            }
            const int vrow = kt2 * 16 + (lane & 15);
#pragma unroll
            for (int gp = 0; gp < 4; ++gp) {
                const int vc0 = 2 * (2 * gp) + (lane >> 4);
                const int vc1 = 2 * (2 * gp + 1) + (lane >> 4);
                u32 vh0[4], vl0[4], vh1[4], vl1[4];
                ldsm4t(vh0, tile_addr(uVhi, vrow, vc0));
                ldsm4t(vl0, tile_addr(uVlo, vrow, vc0));
                ldsm4t(vh1, tile_addr(uVhi, vrow, vc1));
                ldsm4t(vl1, tile_addr(uVlo, vrow, vc1));
                float* o00 = oc[4 * gp];
                float* o01 = oc[4 * gp + 1];
                float* o10 = oc[4 * gp + 2];
                float* o11 = oc[4 * gp + 3];
                mma_bf16(o00, pah, vh0[0], vh0[1]);
                mma_bf16(o01, pah, vh0[2], vh0[3]);
                mma_bf16(o10, pah, vh1[0], vh1[1]);
                mma_bf16(o11, pah, vh1[2], vh1[3]);
                mma_bf16(o00, pah, vl0[0], vl0[1]);
                mma_bf16(o01, pah, vl0[2], vl0[3]);
                mma_bf16(o10, pah, vl1[0], vl1[1]);
                mma_bf16(o11, pah, vl1[2], vl1[3]);
                mma_bf16(o00, pal, vh0[0], vh0[1]);
                mma_bf16(o01, pal, vh0[2], vh0[3]);
                mma_bf16(o10, pal, vh1[0], vh1[1]);
                mma_bf16(o11, pal, vh1[2], vh1[3]);
            }
        }
        __syncthreads();
    }

    // ---- epilogue: normalize + split to bf16 hi/lo directly ----
    {
        float iA = 1.0f / lA, iB = 1.0f / lB;
        int rA = qt_ * 128 + m0 + (lane >> 2);
        int rB = rA + 8;
        size_t baseA = (((size_t)b * T_ + rA) * H_ + h) * D_;
        size_t baseB = (((size_t)b * T_ + rB) * H_ + h) * D_;
        int cb = 2 * (lane & 3);
#pragma unroll
        for (int t = 0; t < 16; ++t) {
            int col = t * 8 + cb;
            u32 hw, lw;
            split_pair(oc[t][0] * iA, oc[t][1] * iA, hw, lw);
            ((u32*)chi)[(baseA + col) >> 1] = hw;
            ((u32*)clo)[(baseA + col) >> 1] = lw;
            split_pair(oc[t][2] * iB, oc[t][3] * iB, hw, lw);
            ((u32*)chi)[(baseB + col) >> 1] = hw;
            ((u32*)clo)[(baseB + col) >> 1] = lw;
        }
    }
}

// ---------------- launch ----------------
extern "C" void kernel_launch(void* const* d_in, const int* in_sizes, int n_in,
                              void* d_out, int out_size)
{
    const float* x  = (const float*)d_in[0];
    const float* wq = (const float*)d_in[2];
    const float* wk = (const float*)d_in[3];
    const float* wv = (const float*)d_in[4];
    const float* wo = (const float*)d_in[5];
    float* out = (float*)d_out;

    u16 *xhi, *xlo, *wqhi, *wqlo, *wkhi, *wklo, *wvhi, *wvlo, *wohi, *wolo;
    u16 *qhi, *qlo, *khi, *klo, *vhi, *vlo, *chi, *clo;
    cudaGetSymbolAddress((void**)&xhi,  g_xhi);
    cudaGetSymbolAddress((void**)&xlo,  g_xlo);
    cudaGetSymbolAddress((void**)&wqhi, g_wqhi);
    cudaGetSymbolAddress((void**)&wqlo, g_wqlo);
    cudaGetSymbolAddress((void**)&wkhi, g_wkhi);
    cudaGetSymbolAddress((void**)&wklo, g_wklo);
    cudaGetSymbolAddress((void**)&wvhi, g_wvhi);
    cudaGetSymbolAddress((void**)&wvlo, g_wvlo);
    cudaGetSymbolAddress((void**)&wohi, g_wohi);
    cudaGetSymbolAddress((void**)&wolo, g_wolo);
    cudaGetSymbolAddress((void**)&qhi,  g_qhi);
    cudaGetSymbolAddress((void**)&qlo,  g_qlo);
    cudaGetSymbolAddress((void**)&khi,  g_khi);
    cudaGetSymbolAddress((void**)&klo,  g_klo);
    cudaGetSymbolAddress((void**)&vhi,  g_vhi);
    cudaGetSymbolAddress((void**)&vlo,  g_vlo);
    cudaGetSymbolAddress((void**)&chi,  g_chi);
    cudaGetSymbolAddress((void**)&clo,  g_clo);

    const int M = B_ * T_;
    const int HD = H_ * D_;
    const int KD = KVH_ * D_;

    cudaFuncSetAttribute(hgemm3_kernel, cudaFuncAttributeMaxDynamicSharedMemorySize, GEMM_SMEM_BYTES);
    cudaFuncSetAttribute(flashmma_kernel, cudaFuncAttributeMaxDynamicSharedMemorySize, FSM_BYTES);

    rope_table_kernel<<<(T_ * 64) / 256, 256>>>();

    split_kernel<<<(M * E_ / 2) / 256, 256>>>(x, xhi, xlo, M * E_ / 2);
    split_kernel<<<(E_ * HD / 2) / 256, 256>>>(wq, wqhi, wqlo, E_ * HD / 2);
    split_kernel<<<(E_ * KD / 2) / 256, 256>>>(wk, wkhi, wklo, E_ * KD / 2);
    split_kernel<<<(E_ * KD / 2) / 256, 256>>>(wv, wvhi, wvlo, E_ * KD / 2);
    split_kernel<<<(HD * E_ / 2) / 256, 256>>>(wo, wohi, wolo, HD * E_ / 2);

    // projections with fused epilogues: q = rope+scale+split, k = rope+split, v = split
    hgemm3_kernel<<<dim3(HD / 128, M / 128), 512, GEMM_SMEM_BYTES>>>(
        xhi, xlo, wqhi, wqlo, (float*)0, qhi, qlo, M, HD, E_, 1);
    hgemm3_kernel<<<dim3(KD / 128, M / 128), 512, GEMM_SMEM_BYTES>>>(
        xhi, xlo, wkhi, wklo, (float*)0, khi, klo, M, KD, E_, 2);
    hgemm3_kernel<<<dim3(KD / 128, M / 128), 512, GEMM_SMEM_BYTES>>>(
        xhi, xlo, wvhi, wvlo, (float*)0, vhi, vlo, M, KD, E_, 3);

    flashmma_kernel<<<dim3(T_ / 128, B_ * H_), 256, FSM_BYTES>>>(
        qhi, qlo, khi, klo, vhi, vlo, chi, clo);

    // output projection (fp32 out)
    hgemm3_kernel<<<dim3(E_ / 128, M / 128), 512, GEMM_SMEM_BYTES>>>(
        chi, clo, wohi, wolo, out, (u16*)0, (u16*)0, M, E_, HD, 0);
}